// round 1
// baseline (speedup 1.0000x reference)
#include <cuda_runtime.h>
#include <math.h>

#define NN 50000
#define NE 400000
#define H  256
#define H3 768
#define NL 8

// ---------------- scratch (static device globals; no runtime alloc) --------
__device__ float g_h0[NN * H];    // dense output = layer0 x
__device__ float g_h1[NN * H];    // layer0 out = layer1 x
__device__ float g_gi[NN * H3];   // x @ w_ih^T + b_ih (per layer)
__device__ float g_gh[NN * H3];   // agg @ w_hh^T + b_hh (per sweep, scattered by node)
__device__ float g_agg[NN * H];   // per-node aggregated messages

__device__ int g_depth[NN];
__device__ int g_indeg[NN];
__device__ int g_csr_off[NN + 1];
__device__ int g_csr_fill[NN];
__device__ int g_csr_src[NE];
__device__ int g_order[NN];       // node ids grouped by sweep
__device__ int g_cnt[NL];         // nodes per sweep
__device__ int g_off[NL + 1];     // exclusive offsets into g_order
__device__ int g_fill[NL];

// ---------------- schedule construction ------------------------------------
__global__ void k_init() {
    int i = blockIdx.x * blockDim.x + threadIdx.x;
    int stride = gridDim.x * blockDim.x;
    for (int n = i; n < NN; n += stride) {
        g_depth[n] = 0;
        g_indeg[n] = 0;
        g_csr_fill[n] = 0;
    }
    if (i < NL) { g_cnt[i] = 0; g_fill[i] = 0; }
}

__global__ void k_relax(const int* __restrict__ E) {
    int i = blockIdx.x * blockDim.x + threadIdx.x;
    int stride = gridDim.x * blockDim.x;
    for (int e = i; e < NE; e += stride) {
        int s = E[e], d = E[NE + e];
        int ds = g_depth[s];
        atomicMax(&g_depth[d], ds + 1);
    }
}

__global__ void k_indeg(const int* __restrict__ E) {
    int i = blockIdx.x * blockDim.x + threadIdx.x;
    int stride = gridDim.x * blockDim.x;
    for (int e = i; e < NE; e += stride)
        atomicAdd(&g_indeg[E[NE + e]], 1);
}

__global__ void k_count() {
    int i = blockIdx.x * blockDim.x + threadIdx.x;
    int stride = gridDim.x * blockDim.x;
    for (int n = i; n < NN; n += stride)
        atomicAdd(&g_cnt[g_depth[n]], 1);
}

__global__ void k_off8() {
    g_off[0] = 0;
    for (int d = 0; d < NL; d++) g_off[d + 1] = g_off[d] + g_cnt[d];
}

// single-block exclusive scan of g_indeg -> g_csr_off
__global__ void k_scan() {
    __shared__ int sh[1024];
    __shared__ int carry;
    int tid = threadIdx.x;
    if (tid == 0) carry = 0;
    __syncthreads();
    for (int base = 0; base < NN; base += 1024) {
        int i = base + tid;
        int v = (i < NN) ? g_indeg[i] : 0;
        sh[tid] = v;
        __syncthreads();
        for (int ofs = 1; ofs < 1024; ofs <<= 1) {
            int t = (tid >= ofs) ? sh[tid - ofs] : 0;
            __syncthreads();
            sh[tid] += t;
            __syncthreads();
        }
        if (i < NN) g_csr_off[i] = carry + sh[tid] - v;
        __syncthreads();
        if (tid == 0) carry += sh[1023];
        __syncthreads();
    }
    if (tid == 0) g_csr_off[NN] = carry;
}

__global__ void k_scatter_node() {
    int i = blockIdx.x * blockDim.x + threadIdx.x;
    int stride = gridDim.x * blockDim.x;
    for (int n = i; n < NN; n += stride) {
        int d = g_depth[n];
        int pos = g_off[d] + atomicAdd(&g_fill[d], 1);
        g_order[pos] = n;
    }
}

__global__ void k_scatter_edge(const int* __restrict__ E) {
    int i = blockIdx.x * blockDim.x + threadIdx.x;
    int stride = gridDim.x * blockDim.x;
    for (int e = i; e < NE; e += stride) {
        int d = E[NE + e];
        int pos = g_csr_off[d] + atomicAdd(&g_csr_fill[d], 1);
        g_csr_src[pos] = E[e];
    }
}

// ---------------- GEMM: C[m][n] = sum_k A[row(m)][k] * W[n][k] + bias[n] ----
// NT gemm, K = 256 fixed. Optional gathered rows: row(m) = order[*offPtr + m]
// (scatter-write C by the same row). M from *cntPtr if given.
// BM=128, BN=64, BK=16, 256 threads, 8x4 micro-tile per thread.
__global__ void gemm_nt(const float* __restrict__ A, const float* __restrict__ W,
                        const float* __restrict__ bias, float* __restrict__ C,
                        const int* __restrict__ order,
                        const int* __restrict__ offPtr,
                        const int* __restrict__ cntPtr, int Mfixed, int Ncols)
{
    __shared__ __align__(16) float As[16][128];
    __shared__ __align__(16) float Ws[16][64];

    int M = cntPtr ? *cntPtr : Mfixed;
    int aoff = offPtr ? *offPtr : 0;

    int tid = threadIdx.x;
    int tx = tid & 15, ty = tid >> 4;
    int aRow = tid >> 2;              // 0..63
    int aK   = (tid & 3) * 4;         // 0,4,8,12
    int cb   = blockIdx.y * 64;

    for (int rb = blockIdx.x; rb * 128 < M; rb += gridDim.x) {
        int row0 = rb * 128;
        int m1 = row0 + aRow, m2 = m1 + 64;
        bool v1 = m1 < M, v2 = m2 < M;
        int r1 = v1 ? (order ? order[aoff + m1] : m1) : 0;
        int r2 = v2 ? (order ? order[aoff + m2] : m2) : 0;

        float acc[8][4];
        #pragma unroll
        for (int i = 0; i < 8; i++)
            #pragma unroll
            for (int j = 0; j < 4; j++) acc[i][j] = 0.f;

        const float* Wp = W + (size_t)(cb + aRow) * H + aK;

        for (int k0 = 0; k0 < H; k0 += 16) {
            float4 a1 = v1 ? *(const float4*)(A + (size_t)r1 * H + k0 + aK)
                           : make_float4(0.f, 0.f, 0.f, 0.f);
            float4 a2 = v2 ? *(const float4*)(A + (size_t)r2 * H + k0 + aK)
                           : make_float4(0.f, 0.f, 0.f, 0.f);
            float4 wv = *(const float4*)(Wp + k0);
            __syncthreads();
            As[aK + 0][aRow] = a1.x; As[aK + 1][aRow] = a1.y;
            As[aK + 2][aRow] = a1.z; As[aK + 3][aRow] = a1.w;
            As[aK + 0][aRow + 64] = a2.x; As[aK + 1][aRow + 64] = a2.y;
            As[aK + 2][aRow + 64] = a2.z; As[aK + 3][aRow + 64] = a2.w;
            Ws[aK + 0][aRow] = wv.x; Ws[aK + 1][aRow] = wv.y;
            Ws[aK + 2][aRow] = wv.z; Ws[aK + 3][aRow] = wv.w;
            __syncthreads();
            #pragma unroll
            for (int kk = 0; kk < 16; kk++) {
                float ar[8], wr[4];
                *(float4*)(ar)     = *(const float4*)&As[kk][ty * 8];
                *(float4*)(ar + 4) = *(const float4*)&As[kk][ty * 8 + 4];
                *(float4*)(wr)     = *(const float4*)&Ws[kk][tx * 4];
                #pragma unroll
                for (int i = 0; i < 8; i++)
                    #pragma unroll
                    for (int j = 0; j < 4; j++)
                        acc[i][j] += ar[i] * wr[j];
            }
        }

        float4 bv = *(const float4*)(bias + cb + tx * 4);
        #pragma unroll
        for (int i = 0; i < 8; i++) {
            int m = row0 + ty * 8 + i;
            if (m < M) {
                int cr = order ? order[aoff + m] : m;
                float4 o;
                o.x = acc[i][0] + bv.x; o.y = acc[i][1] + bv.y;
                o.z = acc[i][2] + bv.z; o.w = acc[i][3] + bv.w;
                *(float4*)(C + (size_t)cr * Ncols + cb + tx * 4) = o;
            }
        }
    }
}

// ---------------- per-sweep message aggregation (CSR gather-sum) -----------
__global__ void k_gather(const float* __restrict__ hsrc, int sweep) {
    int gw = (blockIdx.x * blockDim.x + threadIdx.x) >> 5;
    int nw = (gridDim.x * blockDim.x) >> 5;
    int lane = threadIdx.x & 31;
    int cnt = g_cnt[sweep], base = g_off[sweep];
    for (int i = gw; i < cnt; i += nw) {
        int node = g_order[base + i];
        int e0 = g_csr_off[node], e1 = g_csr_off[node + 1];
        float4 a0 = make_float4(0.f, 0.f, 0.f, 0.f);
        float4 a1 = make_float4(0.f, 0.f, 0.f, 0.f);
        for (int e = e0; e < e1; e++) {
            int src = g_csr_src[e];
            const float4* r = (const float4*)(hsrc + (size_t)src * H);
            float4 x0 = r[lane], x1 = r[lane + 32];
            a0.x += x0.x; a0.y += x0.y; a0.z += x0.z; a0.w += x0.w;
            a1.x += x1.x; a1.y += x1.y; a1.z += x1.z; a1.w += x1.w;
        }
        float4* o = (float4*)(g_agg + (size_t)node * H);
        o[lane] = a0; o[lane + 32] = a1;
    }
}

// ---------------- per-sweep GRU epilogue ------------------------------------
__global__ void k_gru(float* __restrict__ hout, int sweep) {
    int cnt = g_cnt[sweep], base = g_off[sweep];
    int j = threadIdx.x;  // 0..255
    for (int i = blockIdx.x; i < cnt; i += gridDim.x) {
        int node = g_order[base + i];
        const float* gi = g_gi + (size_t)node * H3;
        const float* gh = g_gh + (size_t)node * H3;
        float ir = gi[j], iz = gi[j + H], in_ = gi[j + 2 * H];
        float hr = gh[j], hz = gh[j + H], hn = gh[j + 2 * H];
        float a = g_agg[(size_t)node * H + j];
        float r = 1.f / (1.f + expf(-(ir + hr)));
        float z = 1.f / (1.f + expf(-(iz + hz)));
        float n = tanhf(in_ + r * hn);
        hout[(size_t)node * H + j] = (1.f - z) * n + z * a;
    }
}

// ---------------- launch -----------------------------------------------------
extern "C" void kernel_launch(void* const* d_in, const int* in_sizes, int n_in,
                              void* d_out, int out_size) {
    const float* V   = (const float*)d_in[0];
    const int*   E   = (const int*)d_in[1];
    const float* dw  = (const float*)d_in[2];
    const float* db  = (const float*)d_in[3];
    const float* wih = (const float*)d_in[4];
    const float* whh = (const float*)d_in[5];
    const float* bih = (const float*)d_in[6];
    const float* bhh = (const float*)d_in[7];
    float* out = (float*)d_out;

    float *p_h0, *p_h1, *p_gi, *p_gh, *p_agg;
    int *p_order, *p_cnt, *p_off;
    cudaGetSymbolAddress((void**)&p_h0,  g_h0);
    cudaGetSymbolAddress((void**)&p_h1,  g_h1);
    cudaGetSymbolAddress((void**)&p_gi,  g_gi);
    cudaGetSymbolAddress((void**)&p_gh,  g_gh);
    cudaGetSymbolAddress((void**)&p_agg, g_agg);
    cudaGetSymbolAddress((void**)&p_order, g_order);
    cudaGetSymbolAddress((void**)&p_cnt, g_cnt);
    cudaGetSymbolAddress((void**)&p_off, g_off);

    // ---- schedule (depends only on E; recomputed each launch) ----
    k_init<<<256, 256>>>();
    for (int p = 0; p < NL - 1; p++) k_relax<<<1024, 256>>>(E);
    k_indeg<<<1024, 256>>>(E);
    k_count<<<256, 256>>>();
    k_off8<<<1, 1>>>();
    k_scan<<<1, 1024>>>();
    k_scatter_node<<<256, 256>>>();
    k_scatter_edge<<<1024, 256>>>(E);

    const int MB = (NN + 127) / 128;  // 391

    // ---- dense: h0 = V @ dw^T + db ----
    gemm_nt<<<dim3(MB, 4), 256>>>(V, dw, db, p_h0,
                                  nullptr, nullptr, nullptr, NN, H);

    for (int l = 0; l < 2; l++) {
        const float* xin = l ? p_h1 : p_h0;
        float* hout = l ? out : p_h1;
        const float* wih_l = wih + (size_t)l * H3 * H;
        const float* whh_l = whh + (size_t)l * H3 * H;
        const float* bih_l = bih + (size_t)l * H3;
        const float* bhh_l = bhh + (size_t)l * H3;

        // gi = x @ w_ih^T + b_ih for all nodes (sweep-invariant)
        gemm_nt<<<dim3(MB, 12), 256>>>(xin, wih_l, bih_l, p_gi,
                                       nullptr, nullptr, nullptr, NN, H3);

        for (int s = 0; s < NL; s++) {
            k_gather<<<1024, 256>>>(hout, s);
            gemm_nt<<<dim3(64, 12), 256>>>(p_agg, whh_l, bhh_l, p_gh,
                                           p_order, p_off + s, p_cnt + s,
                                           0, H3);
            k_gru<<<8192, 256>>>(hout, s);
        }
    }
}

// round 6
// speedup vs baseline: 1.0995x; 1.0995x over previous
#include <cuda_runtime.h>
#include <math.h>
#include <stdint.h>

#define NN 50000
#define NE 400000
#define H  256
#define H3 768
#define NL 8

#define GLDA 132   // 128 + 4 pad (floats per smem row)

// ---------------- scratch (static device globals) --------------------------
__device__ float g_h1[NN * H];
__device__ float g_gi[NN * H3];
__device__ float g_gh[NN * H3];
__device__ float g_agg[NN * H];
__device__ float g_m0[H3 * H];   // wih0 @ dw  (fused dense+gi0 weight)
__device__ float g_c0[H3];       // wih0 @ db + bih0

__device__ int g_depth[NN];
__device__ int g_indeg[NN];
__device__ int g_csr_off[NN + 1];
__device__ int g_csr_fill[NN];
__device__ int g_csr_src[NE];
__device__ int g_order[NN];
__device__ int g_cnt[NL];
__device__ int g_off[NL + 1];
__device__ int g_fill[NL];

// ---------------- f32x2 helpers ---------------------------------------------
__device__ __forceinline__ void fma2(unsigned long long& c, unsigned long long a,
                                     unsigned long long b) {
    asm("fma.rn.f32x2 %0, %1, %2, %0;" : "+l"(c) : "l"(a), "l"(b));
}
__device__ __forceinline__ unsigned long long dup2(float v) {
    unsigned long long r;
    asm("mov.b64 %0, {%1, %1};" : "=l"(r) : "f"(v));
    return r;
}
__device__ __forceinline__ float2 unpack2(unsigned long long v) {
    float2 r;
    asm("mov.b64 {%0, %1}, %2;" : "=f"(r.x), "=f"(r.y) : "l"(v));
    return r;
}

// ---------------- schedule construction ------------------------------------
__global__ void k_init() {
    int i = blockIdx.x * blockDim.x + threadIdx.x;
    int stride = gridDim.x * blockDim.x;
    for (int n = i; n < NN; n += stride) {
        g_depth[n] = 0; g_indeg[n] = 0; g_csr_fill[n] = 0;
    }
    if (i < NL) { g_cnt[i] = 0; g_fill[i] = 0; }
}
__global__ void k_relax(const int* __restrict__ E) {
    int i = blockIdx.x * blockDim.x + threadIdx.x;
    int stride = gridDim.x * blockDim.x;
    for (int e = i; e < NE; e += stride) {
        int s = E[e], d = E[NE + e];
        atomicMax(&g_depth[d], g_depth[s] + 1);
    }
}
__global__ void k_indeg(const int* __restrict__ E) {
    int i = blockIdx.x * blockDim.x + threadIdx.x;
    int stride = gridDim.x * blockDim.x;
    for (int e = i; e < NE; e += stride) atomicAdd(&g_indeg[E[NE + e]], 1);
}
__global__ void k_count() {
    int i = blockIdx.x * blockDim.x + threadIdx.x;
    int stride = gridDim.x * blockDim.x;
    for (int n = i; n < NN; n += stride) atomicAdd(&g_cnt[g_depth[n]], 1);
}
__global__ void k_off8() {
    g_off[0] = 0;
    for (int d = 0; d < NL; d++) g_off[d + 1] = g_off[d] + g_cnt[d];
}
__global__ void k_scan() {
    __shared__ int sh[1024];
    __shared__ int carry;
    int tid = threadIdx.x;
    if (tid == 0) carry = 0;
    __syncthreads();
    for (int base = 0; base < NN; base += 1024) {
        int i = base + tid;
        int v = (i < NN) ? g_indeg[i] : 0;
        sh[tid] = v;
        __syncthreads();
        for (int ofs = 1; ofs < 1024; ofs <<= 1) {
            int t = (tid >= ofs) ? sh[tid - ofs] : 0;
            __syncthreads();
            sh[tid] += t;
            __syncthreads();
        }
        if (i < NN) g_csr_off[i] = carry + sh[tid] - v;
        __syncthreads();
        if (tid == 0) carry += sh[1023];
        __syncthreads();
    }
    if (tid == 0) g_csr_off[NN] = carry;
}
__global__ void k_scatter_node() {
    int i = blockIdx.x * blockDim.x + threadIdx.x;
    int stride = gridDim.x * blockDim.x;
    for (int n = i; n < NN; n += stride) {
        int d = g_depth[n];
        int pos = g_off[d] + atomicAdd(&g_fill[d], 1);
        g_order[pos] = n;
    }
}
__global__ void k_scatter_edge(const int* __restrict__ E) {
    int i = blockIdx.x * blockDim.x + threadIdx.x;
    int stride = gridDim.x * blockDim.x;
    for (int e = i; e < NE; e += stride) {
        int d = E[NE + e];
        int pos = g_csr_off[d] + atomicAdd(&g_csr_fill[d], 1);
        g_csr_src[pos] = E[e];
    }
}

// ---------------- fused-weight precompute -----------------------------------
// g_m0[n][j] = sum_k wih0[n][k] * dw[k][j]
__global__ void k_prep(const float* __restrict__ wih0, const float* __restrict__ dw) {
    __shared__ float wrow[H];
    int n = blockIdx.x;       // 0..767
    int j = threadIdx.x;      // 0..255
    wrow[j] = wih0[(size_t)n * H + j];
    __syncthreads();
    float acc = 0.f;
    #pragma unroll 8
    for (int k = 0; k < H; k++) acc = fmaf(wrow[k], dw[(size_t)k * H + j], acc);
    g_m0[(size_t)n * H + j] = acc;
}
// g_c0[n] = sum_k wih0[n][k]*db[k] + bih0[n]
__global__ void k_prep_c(const float* __restrict__ wih0, const float* __restrict__ db,
                         const float* __restrict__ bih0) {
    int n = blockIdx.x * blockDim.x + threadIdx.x;
    if (n < H3) {
        float a = 0.f;
        #pragma unroll 8
        for (int k = 0; k < H; k++) a = fmaf(wih0[(size_t)n * H + k], db[k], a);
        g_c0[n] = a + bih0[n];
    }
}

// ---------------- fp32 NT GEMM via fma.rn.f32x2 ------------------------------
// C[row(m)][cb+n] = sum_k A[row(m)][k] * W[cb+n][k] + bias[cb+n]
// row(m) = order[aoff+m] if order else m.  K = 256 fixed.
// BM=128, BN=128, BK=16, 256 threads, 8x8 microtile (n packed in f32x2 pairs).
__global__ void __launch_bounds__(256)
gemm_f32(const float* __restrict__ A, const float* __restrict__ W,
         const float* __restrict__ bias, float* __restrict__ C,
         const int* __restrict__ order, const int* __restrict__ offPtr,
         const int* __restrict__ cntPtr, int Mfixed, int Ncols)
{
    __shared__ __align__(16) float As[2][16][GLDA];
    __shared__ __align__(16) float Ws[2][16][GLDA];

    const int tid = threadIdx.x;
    const int lane = tid & 31, wid = tid >> 5;
    const int wm = wid >> 1, wn = wid & 1;     // 4x2 warp grid
    const int lm = lane & 3, ln = lane >> 2;   // 4x8 lanes
    const int tm0 = wm * 32 + lm * 8;
    const int tn0 = wn * 64 + ln * 8;

    const int M = cntPtr ? *cntPtr : Mfixed;
    const int aoff = offPtr ? *offPtr : 0;
    const int mtiles = (M + 127) >> 7;
    const int ntiles = Ncols >> 7;
    const int total = mtiles * ntiles;

    for (int t = blockIdx.x; t < total; t += gridDim.x) {
        const int tm = t % mtiles, tn = t / mtiles;
        const int row0 = tm << 7, cb = tn << 7;

        // source pointers (2 float4 loads per operand per stage per thread)
        const float* ap[2]; bool avv[2];
        const float* wp[2];
        #pragma unroll
        for (int i = 0; i < 2; i++) {
            int idx = i * 256 + tid;
            int r = idx >> 2, j = idx & 3;
            int gm = row0 + r;
            avv[i] = gm < M;
            int src = avv[i] ? (order ? order[aoff + gm] : gm) : 0;
            ap[i] = A + (size_t)src * H + j * 4;
            wp[i] = W + (size_t)(cb + r) * H + j * 4;
        }

        float4 ra[2], rw[2];
        #pragma unroll
        for (int i = 0; i < 2; i++) {
            ra[i] = avv[i] ? *(const float4*)(ap[i]) : make_float4(0.f, 0.f, 0.f, 0.f);
            rw[i] = *(const float4*)(wp[i]);
        }
        // store stage 0
        #pragma unroll
        for (int i = 0; i < 2; i++) {
            int idx = i * 256 + tid;
            int r = idx >> 2, j = (idx & 3) * 4;
            As[0][j + 0][r] = ra[i].x; As[0][j + 1][r] = ra[i].y;
            As[0][j + 2][r] = ra[i].z; As[0][j + 3][r] = ra[i].w;
            Ws[0][j + 0][r] = rw[i].x; Ws[0][j + 1][r] = rw[i].y;
            Ws[0][j + 2][r] = rw[i].z; Ws[0][j + 3][r] = rw[i].w;
        }
        __syncthreads();

        unsigned long long acc[8][4];
        #pragma unroll
        for (int i = 0; i < 8; i++)
            #pragma unroll
            for (int j = 0; j < 4; j++) acc[i][j] = 0ULL;

        #pragma unroll 1
        for (int kb = 0; kb < 16; kb++) {
            const int s = kb & 1;
            if (kb < 15) {
                #pragma unroll
                for (int i = 0; i < 2; i++) {
                    ra[i] = avv[i] ? *(const float4*)(ap[i] + (kb + 1) * 16)
                                   : make_float4(0.f, 0.f, 0.f, 0.f);
                    rw[i] = *(const float4*)(wp[i] + (kb + 1) * 16);
                }
            }
            #pragma unroll
            for (int kk = 0; kk < 16; kk++) {
                float4 a0 = *(const float4*)&As[s][kk][tm0];
                float4 a1 = *(const float4*)&As[s][kk][tm0 + 4];
                ulonglong2 b0 = *(const ulonglong2*)&Ws[s][kk][tn0];
                ulonglong2 b1 = *(const ulonglong2*)&Ws[s][kk][tn0 + 4];
                float am[8] = {a0.x, a0.y, a0.z, a0.w, a1.x, a1.y, a1.z, a1.w};
                #pragma unroll
                for (int i = 0; i < 8; i++) {
                    unsigned long long aa = dup2(am[i]);
                    fma2(acc[i][0], aa, b0.x);
                    fma2(acc[i][1], aa, b0.y);
                    fma2(acc[i][2], aa, b1.x);
                    fma2(acc[i][3], aa, b1.y);
                }
            }
            if (kb < 15) {
                const int s2 = (kb + 1) & 1;
                #pragma unroll
                for (int i = 0; i < 2; i++) {
                    int idx = i * 256 + tid;
                    int r = idx >> 2, j = (idx & 3) * 4;
                    As[s2][j + 0][r] = ra[i].x; As[s2][j + 1][r] = ra[i].y;
                    As[s2][j + 2][r] = ra[i].z; As[s2][j + 3][r] = ra[i].w;
                    Ws[s2][j + 0][r] = rw[i].x; Ws[s2][j + 1][r] = rw[i].y;
                    Ws[s2][j + 2][r] = rw[i].z; Ws[s2][j + 3][r] = rw[i].w;
                }
                __syncthreads();
            }
        }

        // epilogue: bias + scatter-store
        float4 bv0 = *(const float4*)(bias + cb + tn0);
        float4 bv1 = *(const float4*)(bias + cb + tn0 + 4);
        #pragma unroll
        for (int i = 0; i < 8; i++) {
            int gm = row0 + tm0 + i;
            if (gm < M) {
                int cr = order ? order[aoff + gm] : gm;
                float* dst = C + (size_t)cr * Ncols + cb + tn0;
                float2 p0 = unpack2(acc[i][0]);
                float2 p1 = unpack2(acc[i][1]);
                float2 p2 = unpack2(acc[i][2]);
                float2 p3 = unpack2(acc[i][3]);
                float4 o0, o1;
                o0.x = p0.x + bv0.x; o0.y = p0.y + bv0.y;
                o0.z = p1.x + bv0.z; o0.w = p1.y + bv0.w;
                o1.x = p2.x + bv1.x; o1.y = p2.y + bv1.y;
                o1.z = p3.x + bv1.z; o1.w = p3.y + bv1.w;
                *(float4*)(dst) = o0;
                *(float4*)(dst + 4) = o1;
            }
        }
        __syncthreads();
    }
}

// ---------------- per-sweep message aggregation (CSR gather-sum) -----------
__global__ void k_gather(const float* __restrict__ hsrc, int sweep) {
    int gw = (blockIdx.x * blockDim.x + threadIdx.x) >> 5;
    int nw = (gridDim.x * blockDim.x) >> 5;
    int lane = threadIdx.x & 31;
    int cnt = g_cnt[sweep], base = g_off[sweep];
    for (int i = gw; i < cnt; i += nw) {
        int node = g_order[base + i];
        int e0 = g_csr_off[node], e1 = g_csr_off[node + 1];
        float4 a0 = make_float4(0.f, 0.f, 0.f, 0.f);
        float4 a1 = make_float4(0.f, 0.f, 0.f, 0.f);
        for (int e = e0; e < e1; e++) {
            int src = g_csr_src[e];
            const float4* r = (const float4*)(hsrc + (size_t)src * H);
            float4 x0 = r[lane], x1 = r[lane + 32];
            a0.x += x0.x; a0.y += x0.y; a0.z += x0.z; a0.w += x0.w;
            a1.x += x1.x; a1.y += x1.y; a1.z += x1.z; a1.w += x1.w;
        }
        float4* o = (float4*)(g_agg + (size_t)node * H);
        o[lane] = a0; o[lane + 32] = a1;
    }
}

// ---------------- per-sweep GRU epilogue ------------------------------------
// per_node: 1 -> gh = ghp + node*H3, a = agg[node];  0 -> gh = ghp (bias), a = 0
__global__ void k_gru(float* __restrict__ hout, int sweep,
                      const float* __restrict__ ghp, int per_node) {
    int cnt = g_cnt[sweep], base = g_off[sweep];
    int j = threadIdx.x;
    for (int i = blockIdx.x; i < cnt; i += gridDim.x) {
        int node = g_order[base + i];
        const float* gi = g_gi + (size_t)node * H3;
        const float* gh = per_node ? (ghp + (size_t)node * H3) : ghp;
        float ir = gi[j], iz = gi[j + H], in_ = gi[j + 2 * H];
        float hr = gh[j], hz = gh[j + H], hn = gh[j + 2 * H];
        float a = per_node ? g_agg[(size_t)node * H + j] : 0.f;
        float r = 1.f / (1.f + expf(-(ir + hr)));
        float z = 1.f / (1.f + expf(-(iz + hz)));
        float n = tanhf(in_ + r * hn);
        hout[(size_t)node * H + j] = (1.f - z) * n + z * a;
    }
}

// ---------------- launch -----------------------------------------------------
extern "C" void kernel_launch(void* const* d_in, const int* in_sizes, int n_in,
                              void* d_out, int out_size) {
    const float* V   = (const float*)d_in[0];
    const int*   E   = (const int*)d_in[1];
    const float* dw  = (const float*)d_in[2];
    const float* db  = (const float*)d_in[3];
    const float* wih = (const float*)d_in[4];
    const float* whh = (const float*)d_in[5];
    const float* bih = (const float*)d_in[6];
    const float* bhh = (const float*)d_in[7];
    float* out = (float*)d_out;

    float *p_h1, *p_gi, *p_gh, *p_agg, *p_m0, *p_c0;
    int *p_order, *p_cnt, *p_off;
    cudaGetSymbolAddress((void**)&p_h1,  g_h1);
    cudaGetSymbolAddress((void**)&p_gi,  g_gi);
    cudaGetSymbolAddress((void**)&p_gh,  g_gh);
    cudaGetSymbolAddress((void**)&p_agg, g_agg);
    cudaGetSymbolAddress((void**)&p_m0,  g_m0);
    cudaGetSymbolAddress((void**)&p_c0,  g_c0);
    cudaGetSymbolAddress((void**)&p_order, g_order);
    cudaGetSymbolAddress((void**)&p_cnt, g_cnt);
    cudaGetSymbolAddress((void**)&p_off, g_off);

    // ---- schedule (depends only on E; recomputed each launch) ----
    k_init<<<256, 256>>>();
    for (int p = 0; p < NL - 1; p++) k_relax<<<1024, 256>>>(E);
    k_indeg<<<1024, 256>>>(E);
    k_count<<<256, 256>>>();
    k_off8<<<1, 1>>>();
    k_scan<<<1, 1024>>>();
    k_scatter_node<<<256, 256>>>();
    k_scatter_edge<<<1024, 256>>>(E);

    // ---- fused dense+gi0 weights ----
    k_prep<<<H3, 256>>>(wih, dw);
    k_prep_c<<<3, 256>>>(wih, db, bih);

    const int GI_TILES = ((NN + 127) / 128) * (H3 / 128);  // 391*6 = 2346

    for (int l = 0; l < 2; l++) {
        float* hout = l ? out : p_h1;
        const float* whh_l = whh + (size_t)l * H3 * H;
        const float* bih_l = bih + (size_t)l * H3;
        const float* bhh_l = bhh + (size_t)l * H3;

        // gi for all nodes (sweep-invariant). Layer 0 uses fused V @ m0^T + c0.
        if (l == 0)
            gemm_f32<<<GI_TILES, 256>>>(V, p_m0, p_c0, p_gi,
                                        nullptr, nullptr, nullptr, NN, H3);
        else
            gemm_f32<<<GI_TILES, 256>>>(p_h1, wih + (size_t)H3 * H, bih_l, p_gi,
                                        nullptr, nullptr, nullptr, NN, H3);

        // sweep 0: agg = 0, h = 0  ->  gh = bhh exactly; skip gather + GEMM
        k_gru<<<2048, 256>>>(hout, 0, bhh_l, 0);

        for (int s = 1; s < NL; s++) {
            k_gather<<<1024, 256>>>(hout, s);
            gemm_f32<<<296, 256>>>(p_agg, whh_l, bhh_l, p_gh,
                                   p_order, p_off + s, p_cnt + s, 0, H3);
            k_gru<<<2048, 256>>>(hout, s, p_gh, 1);
        }
    }
}

// round 7
// speedup vs baseline: 1.2496x; 1.1365x over previous
#include <cuda_runtime.h>
#include <cuda_bf16.h>
#include <math.h>
#include <stdint.h>

#define NN 50000
#define NE 400000
#define H  256
#define H3 768
#define NL 8

#define BM 128
#define BN 64
#define BK 32            // K floats per chunk
#define NCH 8            // 256/32

// smem: rows padded to 80B (32 bf16 = 64B data + 16B pad) -> conflict-free ldmatrix
#define LDA 80
#define ASPL (128 * LDA)             // 10240 per A split
#define WSPL (64 * LDA)              // 5120 per W split
#define OFF_A 0
#define OFF_W (3 * ASPL)             // 30720
#define STAGE (3 * ASPL + 3 * WSPL)  // 46080
#define SMEM_TOT (2 * STAGE)         // 92160

// ---------------- scratch (static device globals) --------------------------
__device__ float g_h1[NN * H];
__device__ float g_gi[NN * H3];
__device__ float g_gh[NN * H3];
__device__ float g_agg[NN * H];
__device__ float g_m0[H3 * H];   // wih0 @ dw  (fused dense+gi0 weight)
__device__ float g_c0[H3];       // wih0 @ db + bih0

__device__ int g_depth[NN];
__device__ int g_indeg[NN];
__device__ int g_csr_off[NN + 1];
__device__ int g_csr_fill[NN];
__device__ int g_csr_src[NE];
__device__ int g_order[NN];
__device__ int g_cnt[NL];
__device__ int g_off[NL + 1];
__device__ int g_fill[NL];

// ---------------- helpers ---------------------------------------------------
__device__ __forceinline__ uint32_t smem_u32(const void* p) {
    uint32_t a;
    asm("{ .reg .u64 t; cvta.to.shared.u64 t, %1; cvt.u32.u64 %0, t; }" : "=r"(a) : "l"(p));
    return a;
}
__device__ __forceinline__ void ldsm4(uint32_t& r0, uint32_t& r1, uint32_t& r2, uint32_t& r3,
                                      uint32_t a) {
    asm volatile("ldmatrix.sync.aligned.m8n8.x4.shared.b16 {%0,%1,%2,%3}, [%4];"
                 : "=r"(r0), "=r"(r1), "=r"(r2), "=r"(r3) : "r"(a));
}
__device__ __forceinline__ void mma16816(float* d, const uint32_t* a, const uint32_t* b) {
    asm volatile(
        "mma.sync.aligned.m16n8k16.row.col.f32.bf16.bf16.f32 "
        "{%0,%1,%2,%3}, {%4,%5,%6,%7}, {%8,%9}, {%0,%1,%2,%3};"
        : "+f"(d[0]), "+f"(d[1]), "+f"(d[2]), "+f"(d[3])
        : "r"(a[0]), "r"(a[1]), "r"(a[2]), "r"(a[3]), "r"(b[0]), "r"(b[1]));
}
// 3-way bf16 split of float4; store pair (8B) per split level at addr + s*dsplit
__device__ __forceinline__ void sts_split3(uint32_t addr, uint32_t dsplit, float4 f) {
    float x = f.x, y = f.y, z = f.z, w = f.w;
    #pragma unroll
    for (int s = 0; s < 3; s++) {
        __nv_bfloat16 hx = __float2bfloat16(x);
        __nv_bfloat16 hy = __float2bfloat16(y);
        __nv_bfloat16 hz = __float2bfloat16(z);
        __nv_bfloat16 hw = __float2bfloat16(w);
        uint32_t q0 = (uint32_t)__bfloat16_as_ushort(hy) << 16 | __bfloat16_as_ushort(hx);
        uint32_t q1 = (uint32_t)__bfloat16_as_ushort(hw) << 16 | __bfloat16_as_ushort(hz);
        asm volatile("st.shared.v2.b32 [%0], {%1,%2};"
                     :: "r"(addr + (uint32_t)s * dsplit), "r"(q0), "r"(q1));
        if (s < 2) {
            x -= __bfloat162float(hx); y -= __bfloat162float(hy);
            z -= __bfloat162float(hz); w -= __bfloat162float(hw);
        }
    }
}

// ---------------- schedule construction ------------------------------------
__global__ void k_init() {
    int i = blockIdx.x * blockDim.x + threadIdx.x;
    int stride = gridDim.x * blockDim.x;
    for (int n = i; n < NN; n += stride) {
        g_depth[n] = 0; g_indeg[n] = 0; g_csr_fill[n] = 0;
    }
    if (i < NL) { g_cnt[i] = 0; g_fill[i] = 0; }
}
__global__ void k_relax(const int* __restrict__ E) {
    int i = blockIdx.x * blockDim.x + threadIdx.x;
    int stride = gridDim.x * blockDim.x;
    for (int e = i; e < NE; e += stride) {
        int s = E[e], d = E[NE + e];
        atomicMax(&g_depth[d], g_depth[s] + 1);
    }
}
__global__ void k_indeg(const int* __restrict__ E) {
    int i = blockIdx.x * blockDim.x + threadIdx.x;
    int stride = gridDim.x * blockDim.x;
    for (int e = i; e < NE; e += stride) atomicAdd(&g_indeg[E[NE + e]], 1);
}
__global__ void k_count() {
    int i = blockIdx.x * blockDim.x + threadIdx.x;
    int stride = gridDim.x * blockDim.x;
    for (int n = i; n < NN; n += stride) atomicAdd(&g_cnt[g_depth[n]], 1);
}
__global__ void k_off8() {
    g_off[0] = 0;
    for (int d = 0; d < NL; d++) g_off[d + 1] = g_off[d] + g_cnt[d];
}
__global__ void k_scan() {
    __shared__ int sh[1024];
    __shared__ int carry;
    int tid = threadIdx.x;
    if (tid == 0) carry = 0;
    __syncthreads();
    for (int base = 0; base < NN; base += 1024) {
        int i = base + tid;
        int v = (i < NN) ? g_indeg[i] : 0;
        sh[tid] = v;
        __syncthreads();
        for (int ofs = 1; ofs < 1024; ofs <<= 1) {
            int t = (tid >= ofs) ? sh[tid - ofs] : 0;
            __syncthreads();
            sh[tid] += t;
            __syncthreads();
        }
        if (i < NN) g_csr_off[i] = carry + sh[tid] - v;
        __syncthreads();
        if (tid == 0) carry += sh[1023];
        __syncthreads();
    }
    if (tid == 0) g_csr_off[NN] = carry;
}
__global__ void k_scatter_node() {
    int i = blockIdx.x * blockDim.x + threadIdx.x;
    int stride = gridDim.x * blockDim.x;
    for (int n = i; n < NN; n += stride) {
        int d = g_depth[n];
        int pos = g_off[d] + atomicAdd(&g_fill[d], 1);
        g_order[pos] = n;
    }
}
__global__ void k_scatter_edge(const int* __restrict__ E) {
    int i = blockIdx.x * blockDim.x + threadIdx.x;
    int stride = gridDim.x * blockDim.x;
    for (int e = i; e < NE; e += stride) {
        int d = E[NE + e];
        int pos = g_csr_off[d] + atomicAdd(&g_csr_fill[d], 1);
        g_csr_src[pos] = E[e];
    }
}

// ---------------- fused-weight precompute -----------------------------------
__global__ void k_prep(const float* __restrict__ wih0, const float* __restrict__ dw) {
    __shared__ float wrow[H];
    int n = blockIdx.x;
    int j = threadIdx.x;
    wrow[j] = wih0[(size_t)n * H + j];
    __syncthreads();
    float acc = 0.f;
    #pragma unroll 8
    for (int k = 0; k < H; k++) acc = fmaf(wrow[k], dw[(size_t)k * H + j], acc);
    g_m0[(size_t)n * H + j] = acc;
}
__global__ void k_prep_c(const float* __restrict__ wih0, const float* __restrict__ db,
                         const float* __restrict__ bih0) {
    int n = blockIdx.x * blockDim.x + threadIdx.x;
    if (n < H3) {
        float a = 0.f;
        #pragma unroll 8
        for (int k = 0; k < H; k++) a = fmaf(wih0[(size_t)n * H + k], db[k], a);
        g_c0[n] = a + bih0[n];
    }
}

// ---------------- bf16 mma.sync NT GEMM (3-way split, 6 products) -----------
// hi*hi product: fresh zero-C mma per step + IEEE-RN scalar accumulation
// (kills the chained-accumulator RZ truncation bias). 5 low-order products
// chain in HW (their magnitude <= 2^-8 of result -> bias negligible).
__global__ void __launch_bounds__(256, 2)
gemm_mma(const float* __restrict__ A, const float* __restrict__ W,
         const float* __restrict__ bias, float* __restrict__ C,
         const int* __restrict__ order, const int* __restrict__ offPtr,
         const int* __restrict__ cntPtr, int Mfixed, int Ncols)
{
    extern __shared__ __align__(128) char smem[];
    const uint32_t sb = smem_u32(smem);

    const int tid = threadIdx.x;
    const int lane = tid & 31;
    const int wid = tid >> 5;
    const int wm = wid & 3;
    const int wn = wid >> 2;

    const int M = cntPtr ? *cntPtr : Mfixed;
    const int aoff = offPtr ? *offPtr : 0;
    const int mtiles = (M + BM - 1) >> 7;
    const int ntiles = Ncols >> 6;
    const int total = mtiles * ntiles;

    uint32_t a_sts[4], w_sts[2];
    #pragma unroll
    for (int i = 0; i < 4; i++) {
        int idx4 = i * 256 + tid;
        a_sts[i] = sb + OFF_A + (uint32_t)((idx4 >> 3) * LDA + (idx4 & 7) * 8);
    }
    #pragma unroll
    for (int i = 0; i < 2; i++) {
        int idx4 = i * 256 + tid;
        w_sts[i] = sb + OFF_W + (uint32_t)((idx4 >> 3) * LDA + (idx4 & 7) * 8);
    }
    uint32_t a_ld[2];
    #pragma unroll
    for (int mt = 0; mt < 2; mt++) {
        int r = wm * 32 + mt * 16 + (lane & 15);
        a_ld[mt] = sb + OFF_A + (uint32_t)(r * LDA + (lane >> 4) * 16);
    }
    uint32_t w_ld[2];
    #pragma unroll
    for (int bp = 0; bp < 2; bp++) {
        int n = wn * 32 + bp * 16 + (lane >> 4) * 8 + (lane & 7);
        int half = (lane >> 3) & 1;
        w_ld[bp] = sb + OFF_W + (uint32_t)(n * LDA + half * 16);
    }

    for (int t = blockIdx.x; t < total; t += gridDim.x) {
        int tm = t % mtiles, tn = t / mtiles;
        int row0 = tm << 7, cb = tn << 6;

        const float* aptr[4]; bool avd[4];
        #pragma unroll
        for (int i = 0; i < 4; i++) {
            int idx4 = i * 256 + tid;
            int gm = row0 + (idx4 >> 3);
            avd[i] = gm < M;
            int src = avd[i] ? (order ? order[aoff + gm] : gm) : 0;
            aptr[i] = A + (size_t)src * H + (idx4 & 7) * 4;
        }
        const float* wptr[2];
        #pragma unroll
        for (int i = 0; i < 2; i++) {
            int idx4 = i * 256 + tid;
            wptr[i] = W + (size_t)(cb + (idx4 >> 3)) * H + (idx4 & 7) * 4;
        }

        float accHH[2][4][4] = {};
        float accLO[2][4][4] = {};

        float4 av[4], wv[2];
        #pragma unroll
        for (int i = 0; i < 4; i++)
            av[i] = avd[i] ? *(const float4*)(aptr[i]) : make_float4(0.f, 0.f, 0.f, 0.f);
        #pragma unroll
        for (int i = 0; i < 2; i++) wv[i] = *(const float4*)(wptr[i]);
        #pragma unroll
        for (int i = 0; i < 4; i++) sts_split3(a_sts[i], ASPL, av[i]);
        #pragma unroll
        for (int i = 0; i < 2; i++) sts_split3(w_sts[i], WSPL, wv[i]);
        __syncthreads();

        #pragma unroll 1
        for (int kc = 0; kc < NCH; kc++) {
            uint32_t st = (uint32_t)((kc & 1) * STAGE);
            if (kc < NCH - 1) {
                #pragma unroll
                for (int i = 0; i < 4; i++)
                    av[i] = avd[i] ? *(const float4*)(aptr[i] + (kc + 1) * BK)
                                   : make_float4(0.f, 0.f, 0.f, 0.f);
                #pragma unroll
                for (int i = 0; i < 2; i++)
                    wv[i] = *(const float4*)(wptr[i] + (kc + 1) * BK);
            }
            #pragma unroll
            for (int ks = 0; ks < 2; ks++) {
                // cache all 3 B splits
                uint32_t bf[3][4][2];
                #pragma unroll
                for (int s = 0; s < 3; s++) {
                    #pragma unroll
                    for (int bp = 0; bp < 2; bp++) {
                        uint32_t wd = w_ld[bp] + st + ks * 32 + (uint32_t)s * WSPL;
                        uint32_t r0, r1, r2, r3;
                        ldsm4(r0, r1, r2, r3, wd);
                        bf[s][bp * 2][0] = r0;  bf[s][bp * 2][1] = r1;
                        bf[s][bp * 2 + 1][0] = r2;  bf[s][bp * 2 + 1][1] = r3;
                    }
                }
                // as=0 (hi): HH via fresh zero-C + scalar add; HM, HL chained
                {
                    uint32_t af[2][4];
                    #pragma unroll
                    for (int mt = 0; mt < 2; mt++) {
                        uint32_t ad = a_ld[mt] + st + ks * 32;
                        ldsm4(af[mt][0], af[mt][1], af[mt][2], af[mt][3], ad);
                    }
                    #pragma unroll
                    for (int mt = 0; mt < 2; mt++)
                        #pragma unroll
                        for (int nt = 0; nt < 4; nt++) {
                            float tmp[4] = {0.f, 0.f, 0.f, 0.f};
                            mma16816(tmp, af[mt], bf[0][nt]);
                            accHH[mt][nt][0] += tmp[0];
                            accHH[mt][nt][1] += tmp[1];
                            accHH[mt][nt][2] += tmp[2];
                            accHH[mt][nt][3] += tmp[3];
                            mma16816(accLO[mt][nt], af[mt], bf[1][nt]);
                            mma16816(accLO[mt][nt], af[mt], bf[2][nt]);
                        }
                }
                // as=1 (mid): MH, MM chained
                {
                    uint32_t af[2][4];
                    #pragma unroll
                    for (int mt = 0; mt < 2; mt++) {
                        uint32_t ad = a_ld[mt] + st + ks * 32 + (uint32_t)ASPL;
                        ldsm4(af[mt][0], af[mt][1], af[mt][2], af[mt][3], ad);
                    }
                    #pragma unroll
                    for (int mt = 0; mt < 2; mt++)
                        #pragma unroll
                        for (int nt = 0; nt < 4; nt++) {
                            mma16816(accLO[mt][nt], af[mt], bf[0][nt]);
                            mma16816(accLO[mt][nt], af[mt], bf[1][nt]);
                        }
                }
                // as=2 (lo): LH chained
                {
                    uint32_t af[2][4];
                    #pragma unroll
                    for (int mt = 0; mt < 2; mt++) {
                        uint32_t ad = a_ld[mt] + st + ks * 32 + 2u * ASPL;
                        ldsm4(af[mt][0], af[mt][1], af[mt][2], af[mt][3], ad);
                    }
                    #pragma unroll
                    for (int mt = 0; mt < 2; mt++)
                        #pragma unroll
                        for (int nt = 0; nt < 4; nt++)
                            mma16816(accLO[mt][nt], af[mt], bf[0][nt]);
                }
            }
            __syncthreads();
            if (kc < NCH - 1) {
                uint32_t stn = (uint32_t)(((kc + 1) & 1) * STAGE);
                #pragma unroll
                for (int i = 0; i < 4; i++) sts_split3(a_sts[i] + stn, ASPL, av[i]);
                #pragma unroll
                for (int i = 0; i < 2; i++) sts_split3(w_sts[i] + stn, WSPL, wv[i]);
                __syncthreads();
            }
        }

        // epilogue: HH + LO + bias, scatter rows
        #pragma unroll
        for (int mt = 0; mt < 2; mt++) {
            #pragma unroll
            for (int p = 0; p < 2; p++) {
                int gm = row0 + wm * 32 + mt * 16 + (lane >> 2) + p * 8;
                if (gm < M) {
                    int cr = order ? order[aoff + gm] : gm;
                    float* dst = C + (size_t)cr * Ncols;
                    #pragma unroll
                    for (int nt = 0; nt < 4; nt++) {
                        int col = cb + wn * 32 + nt * 8 + (lane & 3) * 2;
                        float2 o;
                        o.x = accHH[mt][nt][p * 2 + 0] + accLO[mt][nt][p * 2 + 0]
                            + __ldg(bias + col);
                        o.y = accHH[mt][nt][p * 2 + 1] + accLO[mt][nt][p * 2 + 1]
                            + __ldg(bias + col + 1);
                        *(float2*)(dst + col) = o;
                    }
                }
            }
        }
    }
}

// ---------------- per-sweep message aggregation (CSR gather-sum) -----------
__global__ void k_gather(const float* __restrict__ hsrc, int sweep) {
    int gw = (blockIdx.x * blockDim.x + threadIdx.x) >> 5;
    int nw = (gridDim.x * blockDim.x) >> 5;
    int lane = threadIdx.x & 31;
    int cnt = g_cnt[sweep], base = g_off[sweep];
    for (int i = gw; i < cnt; i += nw) {
        int node = g_order[base + i];
        int e0 = g_csr_off[node], e1 = g_csr_off[node + 1];
        float4 a0 = make_float4(0.f, 0.f, 0.f, 0.f);
        float4 a1 = make_float4(0.f, 0.f, 0.f, 0.f);
        for (int e = e0; e < e1; e++) {
            int src = g_csr_src[e];
            const float4* r = (const float4*)(hsrc + (size_t)src * H);
            float4 x0 = r[lane], x1 = r[lane + 32];
            a0.x += x0.x; a0.y += x0.y; a0.z += x0.z; a0.w += x0.w;
            a1.x += x1.x; a1.y += x1.y; a1.z += x1.z; a1.w += x1.w;
        }
        float4* o = (float4*)(g_agg + (size_t)node * H);
        o[lane] = a0; o[lane + 32] = a1;
    }
}

// ---------------- per-sweep GRU epilogue ------------------------------------
__global__ void k_gru(float* __restrict__ hout, int sweep,
                      const float* __restrict__ ghp, int per_node) {
    int cnt = g_cnt[sweep], base = g_off[sweep];
    int j = threadIdx.x;
    for (int i = blockIdx.x; i < cnt; i += gridDim.x) {
        int node = g_order[base + i];
        const float* gi = g_gi + (size_t)node * H3;
        const float* gh = per_node ? (ghp + (size_t)node * H3) : ghp;
        float ir = gi[j], iz = gi[j + H], in_ = gi[j + 2 * H];
        float hr = gh[j], hz = gh[j + H], hn = gh[j + 2 * H];
        float a = per_node ? g_agg[(size_t)node * H + j] : 0.f;
        float r = 1.f / (1.f + expf(-(ir + hr)));
        float z = 1.f / (1.f + expf(-(iz + hz)));
        float n = tanhf(in_ + r * hn);
        hout[(size_t)node * H + j] = (1.f - z) * n + z * a;
    }
}

// ---------------- launch -----------------------------------------------------
extern "C" void kernel_launch(void* const* d_in, const int* in_sizes, int n_in,
                              void* d_out, int out_size) {
    const float* V   = (const float*)d_in[0];
    const int*   E   = (const int*)d_in[1];
    const float* dw  = (const float*)d_in[2];
    const float* db  = (const float*)d_in[3];
    const float* wih = (const float*)d_in[4];
    const float* whh = (const float*)d_in[5];
    const float* bih = (const float*)d_in[6];
    const float* bhh = (const float*)d_in[7];
    float* out = (float*)d_out;

    float *p_h1, *p_gi, *p_gh, *p_agg, *p_m0, *p_c0;
    int *p_order, *p_cnt, *p_off;
    cudaGetSymbolAddress((void**)&p_h1,  g_h1);
    cudaGetSymbolAddress((void**)&p_gi,  g_gi);
    cudaGetSymbolAddress((void**)&p_gh,  g_gh);
    cudaGetSymbolAddress((void**)&p_agg, g_agg);
    cudaGetSymbolAddress((void**)&p_m0,  g_m0);
    cudaGetSymbolAddress((void**)&p_c0,  g_c0);
    cudaGetSymbolAddress((void**)&p_order, g_order);
    cudaGetSymbolAddress((void**)&p_cnt, g_cnt);
    cudaGetSymbolAddress((void**)&p_off, g_off);

    cudaFuncSetAttribute(gemm_mma, cudaFuncAttributeMaxDynamicSharedMemorySize, SMEM_TOT);

    // ---- schedule (depends only on E; recomputed each launch) ----
    k_init<<<256, 256>>>();
    for (int p = 0; p < NL - 1; p++) k_relax<<<1024, 256>>>(E);
    k_indeg<<<1024, 256>>>(E);
    k_count<<<256, 256>>>();
    k_off8<<<1, 1>>>();
    k_scan<<<1, 1024>>>();
    k_scatter_node<<<256, 256>>>();
    k_scatter_edge<<<1024, 256>>>(E);

    // ---- fused dense+gi0 weights ----
    k_prep<<<H3, 256>>>(wih, dw);
    k_prep_c<<<3, 256>>>(wih, db, bih);

    const int GI_GRID = 1184;

    for (int l = 0; l < 2; l++) {
        float* hout = l ? out : p_h1;
        const float* whh_l = whh + (size_t)l * H3 * H;
        const float* bih_l = bih + (size_t)l * H3;
        const float* bhh_l = bhh + (size_t)l * H3;

        if (l == 0)
            gemm_mma<<<GI_GRID, 256, SMEM_TOT>>>(V, p_m0, p_c0, p_gi,
                                                 nullptr, nullptr, nullptr, NN, H3);
        else
            gemm_mma<<<GI_GRID, 256, SMEM_TOT>>>(p_h1, wih + (size_t)H3 * H, bih_l, p_gi,
                                                 nullptr, nullptr, nullptr, NN, H3);

        // sweep 0: agg = 0, h = 0 -> gh = bhh exactly; skip gather + GEMM
        k_gru<<<2048, 256>>>(hout, 0, bhh_l, 0);

        for (int s = 1; s < NL; s++) {
            k_gather<<<1024, 256>>>(hout, s);
            gemm_mma<<<592, 256, SMEM_TOT>>>(p_agg, whh_l, bhh_l, p_gh,
                                             p_order, p_off + s, p_cnt + s, 0, H3);
            k_gru<<<2048, 256>>>(hout, s, p_gh, 1);
        }
    }
}

// round 9
// speedup vs baseline: 1.3274x; 1.0622x over previous
#include <cuda_runtime.h>
#include <cuda_bf16.h>
#include <math.h>
#include <stdint.h>

#define NN 50000
#define NP (NN + 128)    // pad so OOB tile rows stay inside arrays
#define NE 400000
#define H  256
#define H3 768
#define NL 8

#define BM 128
#define BN 64
#define BK 32
#define NCH 8

// smem: rows padded to 80B (32 bf16 = 64B data + 16B pad) -> conflict-free ldmatrix
#define LDA 80
#define ASPL (128 * LDA)             // 10240 per A plane
#define WSPL (64 * LDA)              // 5120 per W plane
#define OFF_W (3 * ASPL)             // 30720
#define STAGE (3 * ASPL + 3 * WSPL)  // 46080
#define SMEM_TOT (2 * STAGE)         // 92160

// ---------------- scratch (static device globals) --------------------------
__device__ float g_h1[NN * H];
__device__ float g_gi[NN * H3];
__device__ float g_gh[NN * H3];
__device__ float g_agg[NP * H];                 // compacted by sweep order
__device__ float g_m0[H3 * H];
__device__ float g_c0[H3];

__device__ __nv_bfloat16 g_xs[3][NP * H];       // gi-input splits (V, then h1)
__device__ __nv_bfloat16 g_aggs[3][NP * H];     // agg splits (compacted)
__device__ __nv_bfloat16 g_ws[12 * H3 * H];     // 4 W mats x 3 planes

__device__ int g_depth[NN];
__device__ int g_indeg[NN];
__device__ int g_csr_off[NN + 1];
__device__ int g_csr_fill[NN];
__device__ int g_csr_src[NE];
__device__ int g_order[NN];
__device__ int g_cnt[NL];
__device__ int g_off[NL + 1];
__device__ int g_fill[NL];

// ---------------- helpers ---------------------------------------------------
__device__ __forceinline__ uint32_t smem_u32(const void* p) {
    uint32_t a;
    asm("{ .reg .u64 t; cvta.to.shared.u64 t, %1; cvt.u32.u64 %0, t; }" : "=r"(a) : "l"(p));
    return a;
}
__device__ __forceinline__ void ldsm4(uint32_t& r0, uint32_t& r1, uint32_t& r2, uint32_t& r3,
                                      uint32_t a) {
    asm volatile("ldmatrix.sync.aligned.m8n8.x4.shared.b16 {%0,%1,%2,%3}, [%4];"
                 : "=r"(r0), "=r"(r1), "=r"(r2), "=r"(r3) : "r"(a));
}
__device__ __forceinline__ void mma16816(float* d, const uint32_t* a, const uint32_t* b) {
    asm volatile(
        "mma.sync.aligned.m16n8k16.row.col.f32.bf16.bf16.f32 "
        "{%0,%1,%2,%3}, {%4,%5,%6,%7}, {%8,%9}, {%0,%1,%2,%3};"
        : "+f"(d[0]), "+f"(d[1]), "+f"(d[2]), "+f"(d[3])
        : "r"(a[0]), "r"(a[1]), "r"(a[2]), "r"(a[3]), "r"(b[0]), "r"(b[1]));
}
__device__ __forceinline__ void cp16(uint32_t s, const void* g) {
    asm volatile("cp.async.ca.shared.global [%0], [%1], 16;" :: "r"(s), "l"(g) : "memory");
}
__device__ __forceinline__ void split3(float x, __nv_bfloat16& h, __nv_bfloat16& m,
                                       __nv_bfloat16& l) {
    h = __float2bfloat16(x);
    float r = x - __bfloat162float(h);
    m = __float2bfloat16(r);
    r -= __bfloat162float(m);
    l = __float2bfloat16(r);
}
__device__ __forceinline__ uint32_t pack2(__nv_bfloat16 a, __nv_bfloat16 b) {
    return (uint32_t)__bfloat16_as_ushort(b) << 16 | __bfloat16_as_ushort(a);
}

// ---------------- schedule construction ------------------------------------
__global__ void k_init() {
    int i = blockIdx.x * blockDim.x + threadIdx.x;
    int stride = gridDim.x * blockDim.x;
    for (int n = i; n < NN; n += stride) {
        g_depth[n] = 0; g_indeg[n] = 0; g_csr_fill[n] = 0;
    }
    if (i < NL) { g_cnt[i] = 0; g_fill[i] = 0; }
}
__global__ void k_relax(const int* __restrict__ E) {
    int i = blockIdx.x * blockDim.x + threadIdx.x;
    int stride = gridDim.x * blockDim.x;
    for (int e = i; e < NE; e += stride) {
        int s = E[e], d = E[NE + e];
        atomicMax(&g_depth[d], g_depth[s] + 1);
    }
}
__global__ void k_indeg(const int* __restrict__ E) {
    int i = blockIdx.x * blockDim.x + threadIdx.x;
    int stride = gridDim.x * blockDim.x;
    for (int e = i; e < NE; e += stride) atomicAdd(&g_indeg[E[NE + e]], 1);
}
__global__ void k_count() {
    int i = blockIdx.x * blockDim.x + threadIdx.x;
    int stride = gridDim.x * blockDim.x;
    for (int n = i; n < NN; n += stride) atomicAdd(&g_cnt[g_depth[n]], 1);
}
__global__ void k_off8() {
    g_off[0] = 0;
    for (int d = 0; d < NL; d++) g_off[d + 1] = g_off[d] + g_cnt[d];
}
__global__ void k_scan() {
    __shared__ int sh[1024];
    __shared__ int carry;
    int tid = threadIdx.x;
    if (tid == 0) carry = 0;
    __syncthreads();
    for (int base = 0; base < NN; base += 1024) {
        int i = base + tid;
        int v = (i < NN) ? g_indeg[i] : 0;
        sh[tid] = v;
        __syncthreads();
        for (int ofs = 1; ofs < 1024; ofs <<= 1) {
            int t = (tid >= ofs) ? sh[tid - ofs] : 0;
            __syncthreads();
            sh[tid] += t;
            __syncthreads();
        }
        if (i < NN) g_csr_off[i] = carry + sh[tid] - v;
        __syncthreads();
        if (tid == 0) carry += sh[1023];
        __syncthreads();
    }
    if (tid == 0) g_csr_off[NN] = carry;
}
__global__ void k_scatter_node() {
    int i = blockIdx.x * blockDim.x + threadIdx.x;
    int stride = gridDim.x * blockDim.x;
    for (int n = i; n < NN; n += stride) {
        int d = g_depth[n];
        int pos = g_off[d] + atomicAdd(&g_fill[d], 1);
        g_order[pos] = n;
    }
}
__global__ void k_scatter_edge(const int* __restrict__ E) {
    int i = blockIdx.x * blockDim.x + threadIdx.x;
    int stride = gridDim.x * blockDim.x;
    for (int e = i; e < NE; e += stride) {
        int d = E[NE + e];
        int pos = g_csr_off[d] + atomicAdd(&g_csr_fill[d], 1);
        g_csr_src[pos] = E[e];
    }
}

// ---------------- fused-weight precompute + splits ---------------------------
__global__ void k_prep(const float* __restrict__ wih0, const float* __restrict__ dw) {
    __shared__ float wrow[H];
    int n = blockIdx.x;
    int j = threadIdx.x;
    wrow[j] = wih0[(size_t)n * H + j];
    __syncthreads();
    float acc = 0.f;
    #pragma unroll 8
    for (int k = 0; k < H; k++) acc = fmaf(wrow[k], dw[(size_t)k * H + j], acc);
    g_m0[(size_t)n * H + j] = acc;
}
__global__ void k_prep_c(const float* __restrict__ wih0, const float* __restrict__ db,
                         const float* __restrict__ bih0) {
    int n = blockIdx.x * blockDim.x + threadIdx.x;
    if (n < H3) {
        float a = 0.f;
        #pragma unroll 8
        for (int k = 0; k < H; k++) a = fmaf(wih0[(size_t)n * H + k], db[k], a);
        g_c0[n] = a + bih0[n];
    }
}
// vectorized fp32 -> 3 bf16 planes (n4 = elements/4)
__global__ void k_split(const float* __restrict__ src,
                        __nv_bfloat16* __restrict__ dh, __nv_bfloat16* __restrict__ dm,
                        __nv_bfloat16* __restrict__ dl, int n4) {
    int i = blockIdx.x * blockDim.x + threadIdx.x;
    int stride = gridDim.x * blockDim.x;
    for (; i < n4; i += stride) {
        float4 f = ((const float4*)src)[i];
        __nv_bfloat16 h[4], m[4], l[4];
        split3(f.x, h[0], m[0], l[0]);
        split3(f.y, h[1], m[1], l[1]);
        split3(f.z, h[2], m[2], l[2]);
        split3(f.w, h[3], m[3], l[3]);
        uint2 uh = {pack2(h[0], h[1]), pack2(h[2], h[3])};
        uint2 um = {pack2(m[0], m[1]), pack2(m[2], m[3])};
        uint2 ul = {pack2(l[0], l[1]), pack2(l[2], l[3])};
        ((uint2*)dh)[i] = uh;
        ((uint2*)dm)[i] = um;
        ((uint2*)dl)[i] = ul;
    }
}

// ---------------- bf16 GEMM on pre-split planes (6 products) ----------------
// C[aoff+m][cb+n] = sum_k A[aoff+m][k] * W[cb+n][k] + bias[cb+n]; dense, no gather.
__global__ void __launch_bounds__(256, 2)
gemm_mma(const __nv_bfloat16* __restrict__ Ah, const __nv_bfloat16* __restrict__ Am,
         const __nv_bfloat16* __restrict__ Al,
         const __nv_bfloat16* __restrict__ Wh, const __nv_bfloat16* __restrict__ Wm,
         const __nv_bfloat16* __restrict__ Wl,
         const float* __restrict__ bias, float* __restrict__ C,
         const int* __restrict__ offPtr, const int* __restrict__ cntPtr,
         int Mfixed, int Ncols)
{
    extern __shared__ __align__(128) char smem[];
    const uint32_t sb = smem_u32(smem);

    const int tid = threadIdx.x;
    const int lane = tid & 31;
    const int wid = tid >> 5;
    const int wm = wid & 3;
    const int wn = wid >> 2;

    const int M = cntPtr ? *cntPtr : Mfixed;
    const int aoff = offPtr ? *offPtr : 0;
    const int mtiles = (M + 127) >> 7;
    const int ntiles = Ncols >> 6;
    const int total = mtiles * ntiles;

    const __nv_bfloat16* pA[3] = {Ah, Am, Al};
    const __nv_bfloat16* pW[3] = {Wh, Wm, Wl};

    // cp.async 16B unit decomposition (stage-relative smem offsets)
    uint32_t sA[6]; int rA[6], qA[6], plA[6];
    #pragma unroll
    for (int i = 0; i < 6; i++) {
        int u = i * 256 + tid;
        plA[i] = u >> 9; int rem = u & 511; rA[i] = rem >> 2; qA[i] = rem & 3;
        sA[i] = (uint32_t)(plA[i] * ASPL + rA[i] * LDA + qA[i] * 16);
    }
    uint32_t sW[3]; int rW[3], qW[3], plW[3];
    #pragma unroll
    for (int i = 0; i < 3; i++) {
        int u = i * 256 + tid;
        plW[i] = u >> 8; int rem = u & 255; rW[i] = rem >> 2; qW[i] = rem & 3;
        sW[i] = (uint32_t)(OFF_W + plW[i] * WSPL + rW[i] * LDA + qW[i] * 16);
    }

    // ldmatrix bases (hi plane; +s*ASPL / +s*WSPL for other planes) — R7 layout
    uint32_t a_ld[2];
    #pragma unroll
    for (int mt = 0; mt < 2; mt++) {
        int r = wm * 32 + mt * 16 + (lane & 15);
        a_ld[mt] = sb + (uint32_t)(r * LDA + (lane >> 4) * 16);
    }
    uint32_t w_ld[2];
    #pragma unroll
    for (int bp = 0; bp < 2; bp++) {
        int n = wn * 32 + bp * 16 + (lane >> 4) * 8 + (lane & 7);
        int half = (lane >> 3) & 1;
        w_ld[bp] = sb + (uint32_t)(OFF_W + n * LDA + half * 16);
    }

    for (int t = blockIdx.x; t < total; t += gridDim.x) {
        int tm = t % mtiles, tn = t / mtiles;
        int row0 = tm << 7, cb = tn << 6;
        int arow0 = aoff + row0;

        const __nv_bfloat16* gA[6];
        #pragma unroll
        for (int i = 0; i < 6; i++)
            gA[i] = pA[plA[i]] + (size_t)(arow0 + rA[i]) * H + qA[i] * 8;
        const __nv_bfloat16* gW[3];
        #pragma unroll
        for (int i = 0; i < 3; i++)
            gW[i] = pW[plW[i]] + (size_t)(cb + rW[i]) * H + qW[i] * 8;

        // preload chunk 0 -> stage 0
        #pragma unroll
        for (int i = 0; i < 6; i++) cp16(sb + sA[i], gA[i]);
        #pragma unroll
        for (int i = 0; i < 3; i++) cp16(sb + sW[i], gW[i]);
        asm volatile("cp.async.commit_group;" ::: "memory");
        asm volatile("cp.async.wait_group 0;" ::: "memory");
        __syncthreads();

        float accHH[2][4][4] = {};
        float accLO[2][4][4] = {};

        #pragma unroll 1
        for (int kc = 0; kc < NCH; kc++) {
            uint32_t st = (uint32_t)((kc & 1) * STAGE);
            if (kc < NCH - 1) {
                uint32_t stn = (uint32_t)(((kc + 1) & 1) * STAGE);
                #pragma unroll
                for (int i = 0; i < 6; i++) cp16(sb + stn + sA[i], gA[i] + (kc + 1) * 32);
                #pragma unroll
                for (int i = 0; i < 3; i++) cp16(sb + stn + sW[i], gW[i] + (kc + 1) * 32);
                asm volatile("cp.async.commit_group;" ::: "memory");
            }
            #pragma unroll
            for (int ks = 0; ks < 2; ks++) {
                uint32_t bf[3][4][2];
                #pragma unroll
                for (int s = 0; s < 3; s++) {
                    #pragma unroll
                    for (int bp = 0; bp < 2; bp++) {
                        uint32_t wd = w_ld[bp] + st + ks * 32 + (uint32_t)s * WSPL;
                        uint32_t r0, r1, r2, r3;
                        ldsm4(r0, r1, r2, r3, wd);
                        bf[s][bp * 2][0] = r0;  bf[s][bp * 2][1] = r1;
                        bf[s][bp * 2 + 1][0] = r2;  bf[s][bp * 2 + 1][1] = r3;
                    }
                }
                // as=0 (hi): HH fresh zero-C + RN scalar adds; HM, HL chained
                {
                    uint32_t af[2][4];
                    #pragma unroll
                    for (int mt = 0; mt < 2; mt++) {
                        uint32_t ad = a_ld[mt] + st + ks * 32;
                        ldsm4(af[mt][0], af[mt][1], af[mt][2], af[mt][3], ad);
                    }
                    #pragma unroll
                    for (int mt = 0; mt < 2; mt++)
                        #pragma unroll
                        for (int nt = 0; nt < 4; nt++) {
                            float tmp[4] = {0.f, 0.f, 0.f, 0.f};
                            mma16816(tmp, af[mt], bf[0][nt]);
                            accHH[mt][nt][0] += tmp[0];
                            accHH[mt][nt][1] += tmp[1];
                            accHH[mt][nt][2] += tmp[2];
                            accHH[mt][nt][3] += tmp[3];
                            mma16816(accLO[mt][nt], af[mt], bf[1][nt]);
                            mma16816(accLO[mt][nt], af[mt], bf[2][nt]);
                        }
                }
                // as=1 (mid): MH, MM chained
                {
                    uint32_t af[2][4];
                    #pragma unroll
                    for (int mt = 0; mt < 2; mt++) {
                        uint32_t ad = a_ld[mt] + st + ks * 32 + (uint32_t)ASPL;
                        ldsm4(af[mt][0], af[mt][1], af[mt][2], af[mt][3], ad);
                    }
                    #pragma unroll
                    for (int mt = 0; mt < 2; mt++)
                        #pragma unroll
                        for (int nt = 0; nt < 4; nt++) {
                            mma16816(accLO[mt][nt], af[mt], bf[0][nt]);
                            mma16816(accLO[mt][nt], af[mt], bf[1][nt]);
                        }
                }
                // as=2 (lo): LH chained
                {
                    uint32_t af[2][4];
                    #pragma unroll
                    for (int mt = 0; mt < 2; mt++) {
                        uint32_t ad = a_ld[mt] + st + ks * 32 + 2u * ASPL;
                        ldsm4(af[mt][0], af[mt][1], af[mt][2], af[mt][3], ad);
                    }
                    #pragma unroll
                    for (int mt = 0; mt < 2; mt++)
                        #pragma unroll
                        for (int nt = 0; nt < 4; nt++)
                            mma16816(accLO[mt][nt], af[mt], bf[0][nt]);
                }
            }
            if (kc < NCH - 1) {
                asm volatile("cp.async.wait_group 0;" ::: "memory");
                __syncthreads();
            }
        }

        // epilogue: HH + LO + bias
        #pragma unroll
        for (int mt = 0; mt < 2; mt++) {
            #pragma unroll
            for (int p = 0; p < 2; p++) {
                int gm = row0 + wm * 32 + mt * 16 + (lane >> 2) + p * 8;
                if (gm < M) {
                    float* dst = C + (size_t)(aoff + gm) * Ncols;
                    #pragma unroll
                    for (int nt = 0; nt < 4; nt++) {
                        int col = cb + wn * 32 + nt * 8 + (lane & 3) * 2;
                        float2 o;
                        o.x = accHH[mt][nt][p * 2 + 0] + accLO[mt][nt][p * 2 + 0]
                            + __ldg(bias + col);
                        o.y = accHH[mt][nt][p * 2 + 1] + accLO[mt][nt][p * 2 + 1]
                            + __ldg(bias + col + 1);
                        *(float2*)(dst + col) = o;
                    }
                }
            }
        }
    }
}

// ---------------- per-sweep aggregation: fp32 + splits, compacted ------------
__device__ __forceinline__ void store_split4(size_t off, float4 f) {
    __nv_bfloat16 h[4], m[4], l[4];
    split3(f.x, h[0], m[0], l[0]);
    split3(f.y, h[1], m[1], l[1]);
    split3(f.z, h[2], m[2], l[2]);
    split3(f.w, h[3], m[3], l[3]);
    uint2 uh = {pack2(h[0], h[1]), pack2(h[2], h[3])};
    uint2 um = {pack2(m[0], m[1]), pack2(m[2], m[3])};
    uint2 ul = {pack2(l[0], l[1]), pack2(l[2], l[3])};
    *(uint2*)(g_aggs[0] + off) = uh;
    *(uint2*)(g_aggs[1] + off) = um;
    *(uint2*)(g_aggs[2] + off) = ul;
}
__global__ void k_gather(const float* __restrict__ hsrc, int sweep) {
    int gw = (blockIdx.x * blockDim.x + threadIdx.x) >> 5;
    int nw = (gridDim.x * blockDim.x) >> 5;
    int lane = threadIdx.x & 31;
    int cnt = g_cnt[sweep], base = g_off[sweep];
    for (int i = gw; i < cnt; i += nw) {
        int node = g_order[base + i];
        int e0 = g_csr_off[node], e1 = g_csr_off[node + 1];
        float4 a0 = make_float4(0.f, 0.f, 0.f, 0.f);
        float4 a1 = make_float4(0.f, 0.f, 0.f, 0.f);
        for (int e = e0; e < e1; e++) {
            int src = g_csr_src[e];
            const float4* r = (const float4*)(hsrc + (size_t)src * H);
            float4 x0 = r[lane], x1 = r[lane + 32];
            a0.x += x0.x; a0.y += x0.y; a0.z += x0.z; a0.w += x0.w;
            a1.x += x1.x; a1.y += x1.y; a1.z += x1.z; a1.w += x1.w;
        }
        size_t orow = (size_t)(base + i) * H;
        float4* o = (float4*)(g_agg + orow);
        o[lane] = a0; o[lane + 32] = a1;
        store_split4(orow + lane * 4, a0);
        store_split4(orow + 128 + lane * 4, a1);
    }
}

// ---------------- per-sweep GRU epilogue ------------------------------------
__global__ void k_gru(float* __restrict__ hout, int sweep,
                      const float* __restrict__ ghp, int per_node, int wsplit) {
    int cnt = g_cnt[sweep], base = g_off[sweep];
    int j = threadIdx.x;
    for (int i = blockIdx.x; i < cnt; i += gridDim.x) {
        int node = g_order[base + i];
        const float* gi = g_gi + (size_t)node * H3;
        const float* gh = per_node ? (ghp + (size_t)(base + i) * H3) : ghp;
        float ir = gi[j], iz = gi[j + H], in_ = gi[j + 2 * H];
        float hr = gh[j], hz = gh[j + H], hn = gh[j + 2 * H];
        float a = per_node ? g_agg[(size_t)(base + i) * H + j] : 0.f;
        float r = 1.f / (1.f + expf(-(ir + hr)));
        float z = 1.f / (1.f + expf(-(iz + hz)));
        float n = tanhf(in_ + r * hn);
        float hv = (1.f - z) * n + z * a;
        hout[(size_t)node * H + j] = hv;
        if (wsplit) {
            __nv_bfloat16 sh, sm, sl;
            split3(hv, sh, sm, sl);
            size_t o = (size_t)node * H + j;
            g_xs[0][o] = sh; g_xs[1][o] = sm; g_xs[2][o] = sl;
        }
    }
}

// ---------------- launch -----------------------------------------------------
extern "C" void kernel_launch(void* const* d_in, const int* in_sizes, int n_in,
                              void* d_out, int out_size) {
    const float* V   = (const float*)d_in[0];
    const int*   E   = (const int*)d_in[1];
    const float* dw  = (const float*)d_in[2];
    const float* db  = (const float*)d_in[3];
    const float* wih = (const float*)d_in[4];
    const float* whh = (const float*)d_in[5];
    const float* bih = (const float*)d_in[6];
    const float* bhh = (const float*)d_in[7];
    float* out = (float*)d_out;

    float *p_h1, *p_gi, *p_gh, *p_m0, *p_c0;
    __nv_bfloat16 *p_xs, *p_aggs, *p_ws;
    int *p_cnt, *p_off;
    cudaGetSymbolAddress((void**)&p_h1,  g_h1);
    cudaGetSymbolAddress((void**)&p_gi,  g_gi);
    cudaGetSymbolAddress((void**)&p_gh,  g_gh);
    cudaGetSymbolAddress((void**)&p_m0,  g_m0);
    cudaGetSymbolAddress((void**)&p_c0,  g_c0);
    cudaGetSymbolAddress((void**)&p_xs,  g_xs);
    cudaGetSymbolAddress((void**)&p_aggs, g_aggs);
    cudaGetSymbolAddress((void**)&p_ws,  g_ws);
    cudaGetSymbolAddress((void**)&p_cnt, g_cnt);
    cudaGetSymbolAddress((void**)&p_off, g_off);

    cudaFuncSetAttribute(gemm_mma, cudaFuncAttributeMaxDynamicSharedMemorySize, SMEM_TOT);

    // ---- schedule ----
    k_init<<<256, 256>>>();
    for (int p = 0; p < NL - 1; p++) k_relax<<<1024, 256>>>(E);
    k_indeg<<<1024, 256>>>(E);
    k_count<<<256, 256>>>();
    k_off8<<<1, 1>>>();
    k_scan<<<1, 1024>>>();
    k_scatter_node<<<256, 256>>>();
    k_scatter_edge<<<1024, 256>>>(E);

    // ---- fused weights + W splits ----
    k_prep<<<H3, 256>>>(wih, dw);
    k_prep_c<<<3, 256>>>(wih, db, bih);

    const int WN4 = (H3 * H) / 4;
    const size_t WPL = (size_t)H3 * H;
    // mat0 = m0, mat1 = wih1, mat2 = whh0, mat3 = whh1
    k_split<<<512, 256>>>(p_m0, p_ws + 0 * WPL, p_ws + 1 * WPL, p_ws + 2 * WPL, WN4);
    k_split<<<512, 256>>>(wih + WPL, p_ws + 3 * WPL, p_ws + 4 * WPL, p_ws + 5 * WPL, WN4);
    k_split<<<512, 256>>>(whh, p_ws + 6 * WPL, p_ws + 7 * WPL, p_ws + 8 * WPL, WN4);
    k_split<<<512, 256>>>(whh + WPL, p_ws + 9 * WPL, p_ws + 10 * WPL, p_ws + 11 * WPL, WN4);

    // ---- V splits (gi layer-0 input) ----
    const size_t XPL = (size_t)NP * H;
    k_split<<<1024, 256>>>(V, p_xs, p_xs + XPL, p_xs + 2 * XPL, (NN * H) / 4);

    for (int l = 0; l < 2; l++) {
        float* hout = l ? out : p_h1;
        const float* bih_l = bih + (size_t)l * H3;
        const float* bhh_l = bhh + (size_t)l * H3;
        const __nv_bfloat16* wgi = p_ws + (size_t)(l ? 3 : 0) * WPL;
        const __nv_bfloat16* wgh = p_ws + (size_t)(l ? 9 : 6) * WPL;
        const float* gibias = l ? bih_l : p_c0;

        gemm_mma<<<1184, 256, SMEM_TOT>>>(p_xs, p_xs + XPL, p_xs + 2 * XPL,
                                          wgi, wgi + WPL, wgi + 2 * WPL,
                                          gibias, p_gi, nullptr, nullptr, NN, H3);

        // sweep 0: agg = 0 -> gh = bhh exactly
        k_gru<<<2048, 256>>>(hout, 0, bhh_l, 0, l == 0 ? 1 : 0);

        for (int s = 1; s < NL; s++) {
            k_gather<<<1024, 256>>>(hout, s);
            gemm_mma<<<592, 256, SMEM_TOT>>>(p_aggs, p_aggs + XPL, p_aggs + 2 * XPL,
                                             wgh, wgh + WPL, wgh + 2 * WPL,
                                             bhh_l, p_gh, p_off + s, p_cnt + s, 0, H3);
            k_gru<<<2048, 256>>>(hout, s, p_gh, 1, l == 0 ? 1 : 0);
        }
    }
}

// round 11
// speedup vs baseline: 1.4012x; 1.0556x over previous
#include <cuda_runtime.h>
#include <cuda_bf16.h>
#include <math.h>
#include <stdint.h>

#define NN 50000
#define NP (NN + 128)
#define NE 400000
#define H  256
#define H3 768
#define NL 8

#define BM 128
#define BN 64
#define BK 32
#define NCH 8

// smem: rows padded to 80B -> conflict-free ldmatrix
#define LDA 80
#define ASPL (128 * LDA)             // 10240 per A plane
#define WSPL (64 * LDA)              // 5120 per W plane
#define OFF_W (3 * ASPL)             // 30720
#define STAGE (3 * ASPL + 3 * WSPL)  // 46080
#define SMEM_TOT (2 * STAGE)         // 92160

// ---------------- scratch (static device globals) --------------------------
__device__ float g_h1[NN * H];
__device__ float g_gi[NN * H3];
__device__ float g_gh[NN * H3];
__device__ float g_agg[NP * H];
__device__ float g_m0[H3 * H];
__device__ float g_c0[H3];

__device__ __nv_bfloat16 g_xs[3][NP * H];   // gi-input splits (V, then h1)
__device__ __nv_bfloat16 g_aggs[3][NP * H]; // agg splits (compacted)
__device__ __nv_bfloat16 g_ws[12 * H3 * H]; // 4 W mats x 3 planes

__device__ int g_depth[NN];
__device__ int g_indeg[NN];
__device__ int g_csr_off[NN + 1];
__device__ int g_csr_fill[NN];
__device__ int g_csr_src[NE];
__device__ int g_order[NN];
__device__ int g_cnt[NL];
__device__ int g_off[NL + 1];
__device__ int g_fill[NL];

// ---------------- helpers ---------------------------------------------------
__device__ __forceinline__ uint32_t smem_u32(const void* p) {
    uint32_t a;
    asm("{ .reg .u64 t; cvta.to.shared.u64 t, %1; cvt.u32.u64 %0, t; }" : "=r"(a) : "l"(p));
    return a;
}
__device__ __forceinline__ void ldsm4(uint32_t& r0, uint32_t& r1, uint32_t& r2, uint32_t& r3,
                                      uint32_t a) {
    asm volatile("ldmatrix.sync.aligned.m8n8.x4.shared.b16 {%0,%1,%2,%3}, [%4];"
                 : "=r"(r0), "=r"(r1), "=r"(r2), "=r"(r3) : "r"(a));
}
__device__ __forceinline__ void mma16816(float* d, const uint32_t* a, const uint32_t* b) {
    asm volatile(
        "mma.sync.aligned.m16n8k16.row.col.f32.bf16.bf16.f32 "
        "{%0,%1,%2,%3}, {%4,%5,%6,%7}, {%8,%9}, {%0,%1,%2,%3};"
        : "+f"(d[0]), "+f"(d[1]), "+f"(d[2]), "+f"(d[3])
        : "r"(a[0]), "r"(a[1]), "r"(a[2]), "r"(a[3]), "r"(b[0]), "r"(b[1]));
}
__device__ __forceinline__ void cp16(uint32_t s, const void* g) {
    asm volatile("cp.async.ca.shared.global [%0], [%1], 16;" :: "r"(s), "l"(g) : "memory");
}
__device__ __forceinline__ void split3(float x, __nv_bfloat16& h, __nv_bfloat16& m,
                                       __nv_bfloat16& l) {
    h = __float2bfloat16(x);
    float r = x - __bfloat162float(h);
    m = __float2bfloat16(r);
    r -= __bfloat162float(m);
    l = __float2bfloat16(r);
}
__device__ __forceinline__ uint32_t pack2(__nv_bfloat16 a, __nv_bfloat16 b) {
    return (uint32_t)__bfloat16_as_ushort(b) << 16 | __bfloat16_as_ushort(a);
}

// ---------------- schedule construction ------------------------------------
__global__ void k_init() {
    int i = blockIdx.x * blockDim.x + threadIdx.x;
    int stride = gridDim.x * blockDim.x;
    for (int n = i; n < NN; n += stride) {
        g_depth[n] = 0; g_indeg[n] = 0; g_csr_fill[n] = 0;
    }
    if (i < NL) { g_cnt[i] = 0; g_fill[i] = 0; }
}
__global__ void k_relax(const int* __restrict__ E) {
    int i = blockIdx.x * blockDim.x + threadIdx.x;
    int stride = gridDim.x * blockDim.x;
    for (int e = i; e < NE; e += stride) {
        int s = E[e], d = E[NE + e];
        atomicMax(&g_depth[d], g_depth[s] + 1);
    }
}
__global__ void k_indeg(const int* __restrict__ E) {
    int i = blockIdx.x * blockDim.x + threadIdx.x;
    int stride = gridDim.x * blockDim.x;
    for (int e = i; e < NE; e += stride) atomicAdd(&g_indeg[E[NE + e]], 1);
}
__global__ void k_count() {
    int i = blockIdx.x * blockDim.x + threadIdx.x;
    int stride = gridDim.x * blockDim.x;
    for (int n = i; n < NN; n += stride) atomicAdd(&g_cnt[g_depth[n]], 1);
}
__global__ void k_off8() {
    g_off[0] = 0;
    for (int d = 0; d < NL; d++) g_off[d + 1] = g_off[d] + g_cnt[d];
}
__global__ void k_scan() {
    __shared__ int sh[1024];
    __shared__ int carry;
    int tid = threadIdx.x;
    if (tid == 0) carry = 0;
    __syncthreads();
    for (int base = 0; base < NN; base += 1024) {
        int i = base + tid;
        int v = (i < NN) ? g_indeg[i] : 0;
        sh[tid] = v;
        __syncthreads();
        for (int ofs = 1; ofs < 1024; ofs <<= 1) {
            int t = (tid >= ofs) ? sh[tid - ofs] : 0;
            __syncthreads();
            sh[tid] += t;
            __syncthreads();
        }
        if (i < NN) g_csr_off[i] = carry + sh[tid] - v;
        __syncthreads();
        if (tid == 0) carry += sh[1023];
        __syncthreads();
    }
    if (tid == 0) g_csr_off[NN] = carry;
}
__global__ void k_scatter_node() {
    int i = blockIdx.x * blockDim.x + threadIdx.x;
    int stride = gridDim.x * blockDim.x;
    for (int n = i; n < NN; n += stride) {
        int d = g_depth[n];
        int pos = g_off[d] + atomicAdd(&g_fill[d], 1);
        g_order[pos] = n;
    }
}
__global__ void k_scatter_edge(const int* __restrict__ E) {
    int i = blockIdx.x * blockDim.x + threadIdx.x;
    int stride = gridDim.x * blockDim.x;
    for (int e = i; e < NE; e += stride) {
        int d = E[NE + e];
        int pos = g_csr_off[d] + atomicAdd(&g_csr_fill[d], 1);
        g_csr_src[pos] = E[e];
    }
}

// ---------------- fused-weight precompute + splits ---------------------------
__global__ void k_prep(const float* __restrict__ wih0, const float* __restrict__ dw) {
    __shared__ float wrow[H];
    int n = blockIdx.x;
    int j = threadIdx.x;
    wrow[j] = wih0[(size_t)n * H + j];
    __syncthreads();
    float acc = 0.f;
    #pragma unroll 8
    for (int k = 0; k < H; k++) acc = fmaf(wrow[k], dw[(size_t)k * H + j], acc);
    g_m0[(size_t)n * H + j] = acc;
}
__global__ void k_prep_c(const float* __restrict__ wih0, const float* __restrict__ db,
                         const float* __restrict__ bih0) {
    int n = blockIdx.x * blockDim.x + threadIdx.x;
    if (n < H3) {
        float a = 0.f;
        #pragma unroll 8
        for (int k = 0; k < H; k++) a = fmaf(wih0[(size_t)n * H + k], db[k], a);
        g_c0[n] = a + bih0[n];
    }
}
// fp32 -> 3 bf16 planes (n4 = elements/4)
__global__ void k_split(const float* __restrict__ src,
                        __nv_bfloat16* __restrict__ dh, __nv_bfloat16* __restrict__ dm,
                        __nv_bfloat16* __restrict__ dl, int n4) {
    int i = blockIdx.x * blockDim.x + threadIdx.x;
    int stride = gridDim.x * blockDim.x;
    for (; i < n4; i += stride) {
        float4 f = ((const float4*)src)[i];
        __nv_bfloat16 h[4], m[4], l[4];
        split3(f.x, h[0], m[0], l[0]);
        split3(f.y, h[1], m[1], l[1]);
        split3(f.z, h[2], m[2], l[2]);
        split3(f.w, h[3], m[3], l[3]);
        uint2 uh = {pack2(h[0], h[1]), pack2(h[2], h[3])};
        uint2 um = {pack2(m[0], m[1]), pack2(m[2], m[3])};
        uint2 ul = {pack2(l[0], l[1]), pack2(l[2], l[3])};
        ((uint2*)dh)[i] = uh;
        ((uint2*)dm)[i] = um;
        ((uint2*)dl)[i] = ul;
    }
}

// ---------------- bf16 GEMM on pre-split planes (5 products) ----------------
// C[aoff+m][cb+n] = sum_k A[aoff+m][k] * W[cb+n][k] + bias[cb+n]
// HH: fresh zero-C + RN scalar adds. HM, MH, HL, LH chained. MM dropped (2^-18).
__global__ void __launch_bounds__(256, 2)
gemm_mma(const __nv_bfloat16* __restrict__ Ah, const __nv_bfloat16* __restrict__ Am,
         const __nv_bfloat16* __restrict__ Al,
         const __nv_bfloat16* __restrict__ Wh, const __nv_bfloat16* __restrict__ Wm,
         const __nv_bfloat16* __restrict__ Wl,
         const float* __restrict__ bias, float* __restrict__ C,
         const int* __restrict__ offPtr, const int* __restrict__ cntPtr,
         int Mfixed, int Ncols)
{
    extern __shared__ __align__(128) char smem[];
    const uint32_t sb = smem_u32(smem);

    const int tid = threadIdx.x;
    const int lane = tid & 31;
    const int wid = tid >> 5;
    const int wm = wid & 3;
    const int wn = wid >> 2;

    const int M = cntPtr ? *cntPtr : Mfixed;
    const int aoff = offPtr ? *offPtr : 0;
    const int mtiles = (M + 127) >> 7;
    const int ntiles = Ncols >> 6;
    const int total = mtiles * ntiles;

    const __nv_bfloat16* pA[3] = {Ah, Am, Al};
    const __nv_bfloat16* pW[3] = {Wh, Wm, Wl};

    uint32_t sA[6]; int rA[6], qA[6], plA[6];
    #pragma unroll
    for (int i = 0; i < 6; i++) {
        int u = i * 256 + tid;
        plA[i] = u >> 9; int rem = u & 511; rA[i] = rem >> 2; qA[i] = rem & 3;
        sA[i] = (uint32_t)(plA[i] * ASPL + rA[i] * LDA + qA[i] * 16);
    }
    uint32_t sW[3]; int rW[3], qW[3], plW[3];
    #pragma unroll
    for (int i = 0; i < 3; i++) {
        int u = i * 256 + tid;
        plW[i] = u >> 8; int rem = u & 255; rW[i] = rem >> 2; qW[i] = rem & 3;
        sW[i] = (uint32_t)(OFF_W + plW[i] * WSPL + rW[i] * LDA + qW[i] * 16);
    }

    uint32_t a_ld[2];
    #pragma unroll
    for (int mt = 0; mt < 2; mt++) {
        int r = wm * 32 + mt * 16 + (lane & 15);
        a_ld[mt] = sb + (uint32_t)(r * LDA + (lane >> 4) * 16);
    }
    uint32_t w_ld[2];
    #pragma unroll
    for (int bp = 0; bp < 2; bp++) {
        int n = wn * 32 + bp * 16 + (lane >> 4) * 8 + (lane & 7);
        int half = (lane >> 3) & 1;
        w_ld[bp] = sb + (uint32_t)(OFF_W + n * LDA + half * 16);
    }

    for (int t = blockIdx.x; t < total; t += gridDim.x) {
        int tm = t % mtiles, tn = t / mtiles;
        int row0 = tm << 7, cb = tn << 6;
        int arow0 = aoff + row0;

        const __nv_bfloat16* gA[6];
        #pragma unroll
        for (int i = 0; i < 6; i++)
            gA[i] = pA[plA[i]] + (size_t)(arow0 + rA[i]) * H + qA[i] * 8;
        const __nv_bfloat16* gW[3];
        #pragma unroll
        for (int i = 0; i < 3; i++)
            gW[i] = pW[plW[i]] + (size_t)(cb + rW[i]) * H + qW[i] * 8;

        #pragma unroll
        for (int i = 0; i < 6; i++) cp16(sb + sA[i], gA[i]);
        #pragma unroll
        for (int i = 0; i < 3; i++) cp16(sb + sW[i], gW[i]);
        asm volatile("cp.async.commit_group;" ::: "memory");
        asm volatile("cp.async.wait_group 0;" ::: "memory");
        __syncthreads();

        float accHH[2][4][4] = {};
        float accLO[2][4][4] = {};

        #pragma unroll 1
        for (int kc = 0; kc < NCH; kc++) {
            uint32_t st = (uint32_t)((kc & 1) * STAGE);
            if (kc < NCH - 1) {
                uint32_t stn = (uint32_t)(((kc + 1) & 1) * STAGE);
                #pragma unroll
                for (int i = 0; i < 6; i++) cp16(sb + stn + sA[i], gA[i] + (kc + 1) * 32);
                #pragma unroll
                for (int i = 0; i < 3; i++) cp16(sb + stn + sW[i], gW[i] + (kc + 1) * 32);
                asm volatile("cp.async.commit_group;" ::: "memory");
            }
            #pragma unroll
            for (int ks = 0; ks < 2; ks++) {
                uint32_t bf[3][4][2];
                #pragma unroll
                for (int s = 0; s < 3; s++) {
                    #pragma unroll
                    for (int bp = 0; bp < 2; bp++) {
                        uint32_t wd = w_ld[bp] + st + ks * 32 + (uint32_t)s * WSPL;
                        uint32_t r0, r1, r2, r3;
                        ldsm4(r0, r1, r2, r3, wd);
                        bf[s][bp * 2][0] = r0;  bf[s][bp * 2][1] = r1;
                        bf[s][bp * 2 + 1][0] = r2;  bf[s][bp * 2 + 1][1] = r3;
                    }
                }
                // A hi: HH fresh + HM, HL chained
                {
                    uint32_t af[2][4];
                    #pragma unroll
                    for (int mt = 0; mt < 2; mt++) {
                        uint32_t ad = a_ld[mt] + st + ks * 32;
                        ldsm4(af[mt][0], af[mt][1], af[mt][2], af[mt][3], ad);
                    }
                    #pragma unroll
                    for (int mt = 0; mt < 2; mt++)
                        #pragma unroll
                        for (int nt = 0; nt < 4; nt++) {
                            float tmp[4] = {0.f, 0.f, 0.f, 0.f};
                            mma16816(tmp, af[mt], bf[0][nt]);
                            accHH[mt][nt][0] += tmp[0];
                            accHH[mt][nt][1] += tmp[1];
                            accHH[mt][nt][2] += tmp[2];
                            accHH[mt][nt][3] += tmp[3];
                            mma16816(accLO[mt][nt], af[mt], bf[1][nt]);
                            mma16816(accLO[mt][nt], af[mt], bf[2][nt]);
                        }
                }
                // A mid: MH chained (MM dropped)
                {
                    uint32_t af[2][4];
                    #pragma unroll
                    for (int mt = 0; mt < 2; mt++) {
                        uint32_t ad = a_ld[mt] + st + ks * 32 + (uint32_t)ASPL;
                        ldsm4(af[mt][0], af[mt][1], af[mt][2], af[mt][3], ad);
                    }
                    #pragma unroll
                    for (int mt = 0; mt < 2; mt++)
                        #pragma unroll
                        for (int nt = 0; nt < 4; nt++)
                            mma16816(accLO[mt][nt], af[mt], bf[0][nt]);
                }
                // A lo: LH chained
                {
                    uint32_t af[2][4];
                    #pragma unroll
                    for (int mt = 0; mt < 2; mt++) {
                        uint32_t ad = a_ld[mt] + st + ks * 32 + 2u * ASPL;
                        ldsm4(af[mt][0], af[mt][1], af[mt][2], af[mt][3], ad);
                    }
                    #pragma unroll
                    for (int mt = 0; mt < 2; mt++)
                        #pragma unroll
                        for (int nt = 0; nt < 4; nt++)
                            mma16816(accLO[mt][nt], af[mt], bf[0][nt]);
                }
            }
            if (kc < NCH - 1) {
                asm volatile("cp.async.wait_group 0;" ::: "memory");
                __syncthreads();
            }
        }

        // epilogue: HH + LO + bias
        #pragma unroll
        for (int mt = 0; mt < 2; mt++) {
            #pragma unroll
            for (int p = 0; p < 2; p++) {
                int gm = row0 + wm * 32 + mt * 16 + (lane >> 2) + p * 8;
                if (gm < M) {
                    float* dst = C + (size_t)(aoff + gm) * Ncols;
                    #pragma unroll
                    for (int nt = 0; nt < 4; nt++) {
                        int col = cb + wn * 32 + nt * 8 + (lane & 3) * 2;
                        float2 o;
                        o.x = accHH[mt][nt][p * 2 + 0] + accLO[mt][nt][p * 2 + 0]
                            + __ldg(bias + col);
                        o.y = accHH[mt][nt][p * 2 + 1] + accLO[mt][nt][p * 2 + 1]
                            + __ldg(bias + col + 1);
                        *(float2*)(dst + col) = o;
                    }
                }
            }
        }
    }
}

// ---------------- per-sweep aggregation: fp32 + splits, compacted ------------
__device__ __forceinline__ void store_split4(size_t off, float4 f) {
    __nv_bfloat16 h[4], m[4], l[4];
    split3(f.x, h[0], m[0], l[0]);
    split3(f.y, h[1], m[1], l[1]);
    split3(f.z, h[2], m[2], l[2]);
    split3(f.w, h[3], m[3], l[3]);
    uint2 uh = {pack2(h[0], h[1]), pack2(h[2], h[3])};
    uint2 um = {pack2(m[0], m[1]), pack2(m[2], m[3])};
    uint2 ul = {pack2(l[0], l[1]), pack2(l[2], l[3])};
    *(uint2*)(g_aggs[0] + off) = uh;
    *(uint2*)(g_aggs[1] + off) = um;
    *(uint2*)(g_aggs[2] + off) = ul;
}
__global__ void k_gather(const float* __restrict__ hsrc, int sweep) {
    int gw = (blockIdx.x * blockDim.x + threadIdx.x) >> 5;
    int nw = (gridDim.x * blockDim.x) >> 5;
    int lane = threadIdx.x & 31;
    int cnt = g_cnt[sweep], base = g_off[sweep];
    for (int i = gw; i < cnt; i += nw) {
        int node = g_order[base + i];
        int e0 = g_csr_off[node], e1 = g_csr_off[node + 1];
        float4 a0 = make_float4(0.f, 0.f, 0.f, 0.f);
        float4 a1 = make_float4(0.f, 0.f, 0.f, 0.f);
        for (int e = e0; e < e1; e++) {
            int src = g_csr_src[e];
            const float4* r = (const float4*)(hsrc + (size_t)src * H);
            float4 x0 = r[lane], x1 = r[lane + 32];
            a0.x += x0.x; a0.y += x0.y; a0.z += x0.z; a0.w += x0.w;
            a1.x += x1.x; a1.y += x1.y; a1.z += x1.z; a1.w += x1.w;
        }
        size_t orow = (size_t)(base + i) * H;
        float4* o = (float4*)(g_agg + orow);
        o[lane] = a0; o[lane + 32] = a1;
        store_split4(orow + lane * 4, a0);
        store_split4(orow + 128 + lane * 4, a1);
    }
}

// ---------------- per-sweep GRU epilogue ------------------------------------
__global__ void k_gru(float* __restrict__ hout, int sweep,
                      const float* __restrict__ ghp, int per_node, int wsplit) {
    int cnt = g_cnt[sweep], base = g_off[sweep];
    int j = threadIdx.x;
    for (int i = blockIdx.x; i < cnt; i += gridDim.x) {
        int node = g_order[base + i];
        const float* gi = g_gi + (size_t)node * H3;
        const float* gh = per_node ? (ghp + (size_t)(base + i) * H3) : ghp;
        float ir = gi[j], iz = gi[j + H], in_ = gi[j + 2 * H];
        float hr = gh[j], hz = gh[j + H], hn = gh[j + 2 * H];
        float a = per_node ? g_agg[(size_t)(base + i) * H + j] : 0.f;
        float r = 1.f / (1.f + expf(-(ir + hr)));
        float z = 1.f / (1.f + expf(-(iz + hz)));
        float n = tanhf(in_ + r * hn);
        float hv = (1.f - z) * n + z * a;
        hout[(size_t)node * H + j] = hv;
        if (wsplit) {
            __nv_bfloat16 sh, sm, sl;
            split3(hv, sh, sm, sl);
            size_t o = (size_t)node * H + j;
            g_xs[0][o] = sh; g_xs[1][o] = sm; g_xs[2][o] = sl;
        }
    }
}

// ---------------- launch -----------------------------------------------------
extern "C" void kernel_launch(void* const* d_in, const int* in_sizes, int n_in,
                              void* d_out, int out_size) {
    const float* V   = (const float*)d_in[0];
    const int*   E   = (const int*)d_in[1];
    const float* dw  = (const float*)d_in[2];
    const float* db  = (const float*)d_in[3];
    const float* wih = (const float*)d_in[4];
    const float* whh = (const float*)d_in[5];
    const float* bih = (const float*)d_in[6];
    const float* bhh = (const float*)d_in[7];
    float* out = (float*)d_out;

    float *p_h1, *p_gi, *p_gh, *p_m0, *p_c0;
    __nv_bfloat16 *p_xs, *p_aggs, *p_ws;
    int *p_cnt, *p_off;
    cudaGetSymbolAddress((void**)&p_h1,  g_h1);
    cudaGetSymbolAddress((void**)&p_gi,  g_gi);
    cudaGetSymbolAddress((void**)&p_gh,  g_gh);
    cudaGetSymbolAddress((void**)&p_m0,  g_m0);
    cudaGetSymbolAddress((void**)&p_c0,  g_c0);
    cudaGetSymbolAddress((void**)&p_xs,  g_xs);
    cudaGetSymbolAddress((void**)&p_aggs, g_aggs);
    cudaGetSymbolAddress((void**)&p_ws,  g_ws);
    cudaGetSymbolAddress((void**)&p_cnt, g_cnt);
    cudaGetSymbolAddress((void**)&p_off, g_off);

    cudaFuncSetAttribute(gemm_mma, cudaFuncAttributeMaxDynamicSharedMemorySize, SMEM_TOT);

    // ---- schedule ----
    k_init<<<256, 256>>>();
    for (int p = 0; p < NL - 1; p++) k_relax<<<1024, 256>>>(E);
    k_indeg<<<1024, 256>>>(E);
    k_count<<<256, 256>>>();
    k_off8<<<1, 1>>>();
    k_scan<<<1, 1024>>>();
    k_scatter_node<<<256, 256>>>();
    k_scatter_edge<<<1024, 256>>>(E);

    // ---- fused weights + W splits ----
    k_prep<<<H3, 256>>>(wih, dw);
    k_prep_c<<<3, 256>>>(wih, db, bih);

    const int WN4 = (H3 * H) / 4;
    const size_t WPL = (size_t)H3 * H;
    k_split<<<512, 256>>>(p_m0, p_ws + 0 * WPL, p_ws + 1 * WPL, p_ws + 2 * WPL, WN4);
    k_split<<<512, 256>>>(wih + WPL, p_ws + 3 * WPL, p_ws + 4 * WPL, p_ws + 5 * WPL, WN4);
    k_split<<<512, 256>>>(whh, p_ws + 6 * WPL, p_ws + 7 * WPL, p_ws + 8 * WPL, WN4);
    k_split<<<512, 256>>>(whh + WPL, p_ws + 9 * WPL, p_ws + 10 * WPL, p_ws + 11 * WPL, WN4);

    // ---- V splits ----
    const size_t XPL = (size_t)NP * H;
    k_split<<<1024, 256>>>(V, p_xs, p_xs + XPL, p_xs + 2 * XPL, (NN * H) / 4);

    for (int l = 0; l < 2; l++) {
        float* hout = l ? out : p_h1;
        const float* bih_l = bih + (size_t)l * H3;
        const float* bhh_l = bhh + (size_t)l * H3;
        const __nv_bfloat16* wgi = p_ws + (size_t)(l ? 3 : 0) * WPL;
        const __nv_bfloat16* wgh = p_ws + (size_t)(l ? 9 : 6) * WPL;
        const float* gibias = l ? bih_l : p_c0;

        gemm_mma<<<1184, 256, SMEM_TOT>>>(p_xs, p_xs + XPL, p_xs + 2 * XPL,
                                          wgi, wgi + WPL, wgi + 2 * WPL,
                                          gibias, p_gi, nullptr, nullptr, NN, H3);

        // sweep 0: agg = 0 -> gh = bhh exactly
        k_gru<<<2048, 256>>>(hout, 0, bhh_l, 0, l == 0 ? 1 : 0);

        for (int s = 1; s < NL; s++) {
            k_gather<<<1024, 256>>>(hout, s);
            gemm_mma<<<592, 256, SMEM_TOT>>>(p_aggs, p_aggs + XPL, p_aggs + 2 * XPL,
                                             wgh, wgh + WPL, wgh + 2 * WPL,
                                             bhh_l, p_gh, p_off + s, p_cnt + s, 0, H3);
            k_gru<<<2048, 256>>>(hout, s, p_gh, 1, l == 0 ? 1 : 0);
        }
    }
}

// round 12
// speedup vs baseline: 1.8221x; 1.3004x over previous
#include <cuda_runtime.h>
#include <cuda_fp16.h>
#include <math.h>
#include <stdint.h>

#define NN 50000
#define NP (NN + 128)
#define NE 400000
#define H  256
#define H3 768
#define NL 8

#define BM 128
#define BN 64
#define BK 32
#define NCH 8

// smem: rows padded to 80B -> conflict-free ldmatrix
#define LDA 80
#define ASPL (128 * LDA)             // 10240 per A plane
#define WSPL (64 * LDA)              // 5120 per W plane
#define OFF_W (2 * ASPL)             // 20480
#define STAGE (2 * ASPL + 2 * WSPL)  // 30720
#define SMEM_TOT (2 * STAGE)         // 61440

#define ASCALE (1.0f / 4096.0f)      // A-side pre-scale (2^-12)
#define LOSC   2048.0f               // lo-plane boost (2^11)

// ---------------- scratch (static device globals) --------------------------
__device__ float g_h1[NN * H];
__device__ float g_gi[NN * H3];
__device__ float g_gh[NN * H3];
__device__ float g_agg[NP * H];
__device__ float g_m0[H3 * H];
__device__ float g_c0[H3];

__device__ __half g_xs[2][NP * H];   // gi-input splits (scaled by 2^-12)
__device__ __half g_aggs[2][NP * H]; // agg splits (scaled, compacted)
__device__ __half g_ws[8 * H3 * H];  // 4 W mats x 2 planes (unscaled)

__device__ int g_depth[NN];
__device__ int g_indeg[NN];
__device__ int g_csr_off[NN + 1];
__device__ int g_csr_fill[NN];
__device__ int g_csr_src[NE];
__device__ int g_order[NN];
__device__ int g_cnt[NL];
__device__ int g_off[NL + 1];
__device__ int g_fill[NL];

// ---------------- helpers ---------------------------------------------------
__device__ __forceinline__ uint32_t smem_u32(const void* p) {
    uint32_t a;
    asm("{ .reg .u64 t; cvta.to.shared.u64 t, %1; cvt.u32.u64 %0, t; }" : "=r"(a) : "l"(p));
    return a;
}
__device__ __forceinline__ void ldsm4(uint32_t& r0, uint32_t& r1, uint32_t& r2, uint32_t& r3,
                                      uint32_t a) {
    asm volatile("ldmatrix.sync.aligned.m8n8.x4.shared.b16 {%0,%1,%2,%3}, [%4];"
                 : "=r"(r0), "=r"(r1), "=r"(r2), "=r"(r3) : "r"(a));
}
__device__ __forceinline__ void mma16816(float* d, const uint32_t* a, const uint32_t* b) {
    asm volatile(
        "mma.sync.aligned.m16n8k16.row.col.f32.f16.f16.f32 "
        "{%0,%1,%2,%3}, {%4,%5,%6,%7}, {%8,%9}, {%0,%1,%2,%3};"
        : "+f"(d[0]), "+f"(d[1]), "+f"(d[2]), "+f"(d[3])
        : "r"(a[0]), "r"(a[1]), "r"(a[2]), "r"(a[3]), "r"(b[0]), "r"(b[1]));
}
__device__ __forceinline__ void cp16(uint32_t s, const void* g) {
    asm volatile("cp.async.ca.shared.global [%0], [%1], 16;" :: "r"(s), "l"(g) : "memory");
}
// 2-way fp16 split with pre-scale: h = rn(x*pre), l = rn((x*pre - h)*2048)
__device__ __forceinline__ void split2s(float x, float pre, __half& h, __half& l) {
    float xs = x * pre;
    h = __float2half_rn(xs);
    l = __float2half_rn((xs - __half2float(h)) * LOSC);
}
__device__ __forceinline__ uint32_t pack2h(__half a, __half b) {
    return (uint32_t)__half_as_ushort(b) << 16 | __half_as_ushort(a);
}

// ---------------- schedule construction ------------------------------------
__global__ void k_init() {
    int i = blockIdx.x * blockDim.x + threadIdx.x;
    int stride = gridDim.x * blockDim.x;
    for (int n = i; n < NN; n += stride) {
        g_depth[n] = 0; g_indeg[n] = 0; g_csr_fill[n] = 0;
    }
    if (i < NL) { g_cnt[i] = 0; g_fill[i] = 0; }
}
__global__ void k_relax(const int* __restrict__ E) {
    int i = blockIdx.x * blockDim.x + threadIdx.x;
    int stride = gridDim.x * blockDim.x;
    for (int e = i; e < NE; e += stride) {
        int s = E[e], d = E[NE + e];
        atomicMax(&g_depth[d], g_depth[s] + 1);
    }
}
__global__ void k_indeg(const int* __restrict__ E) {
    int i = blockIdx.x * blockDim.x + threadIdx.x;
    int stride = gridDim.x * blockDim.x;
    for (int e = i; e < NE; e += stride) atomicAdd(&g_indeg[E[NE + e]], 1);
}
__global__ void k_count() {
    int i = blockIdx.x * blockDim.x + threadIdx.x;
    int stride = gridDim.x * blockDim.x;
    for (int n = i; n < NN; n += stride) atomicAdd(&g_cnt[g_depth[n]], 1);
}
__global__ void k_off8() {
    g_off[0] = 0;
    for (int d = 0; d < NL; d++) g_off[d + 1] = g_off[d] + g_cnt[d];
}
__global__ void k_scan() {
    __shared__ int sh[1024];
    __shared__ int carry;
    int tid = threadIdx.x;
    if (tid == 0) carry = 0;
    __syncthreads();
    for (int base = 0; base < NN; base += 1024) {
        int i = base + tid;
        int v = (i < NN) ? g_indeg[i] : 0;
        sh[tid] = v;
        __syncthreads();
        for (int ofs = 1; ofs < 1024; ofs <<= 1) {
            int t = (tid >= ofs) ? sh[tid - ofs] : 0;
            __syncthreads();
            sh[tid] += t;
            __syncthreads();
        }
        if (i < NN) g_csr_off[i] = carry + sh[tid] - v;
        __syncthreads();
        if (tid == 0) carry += sh[1023];
        __syncthreads();
    }
    if (tid == 0) g_csr_off[NN] = carry;
}
__global__ void k_scatter_node() {
    int i = blockIdx.x * blockDim.x + threadIdx.x;
    int stride = gridDim.x * blockDim.x;
    for (int n = i; n < NN; n += stride) {
        int d = g_depth[n];
        int pos = g_off[d] + atomicAdd(&g_fill[d], 1);
        g_order[pos] = n;
    }
}
__global__ void k_scatter_edge(const int* __restrict__ E) {
    int i = blockIdx.x * blockDim.x + threadIdx.x;
    int stride = gridDim.x * blockDim.x;
    for (int e = i; e < NE; e += stride) {
        int d = E[NE + e];
        int pos = g_csr_off[d] + atomicAdd(&g_csr_fill[d], 1);
        g_csr_src[pos] = E[e];
    }
}

// ---------------- fused-weight precompute + splits ---------------------------
__global__ void k_prep(const float* __restrict__ wih0, const float* __restrict__ dw) {
    __shared__ float wrow[H];
    int n = blockIdx.x;
    int j = threadIdx.x;
    wrow[j] = wih0[(size_t)n * H + j];
    __syncthreads();
    float acc = 0.f;
    #pragma unroll 8
    for (int k = 0; k < H; k++) acc = fmaf(wrow[k], dw[(size_t)k * H + j], acc);
    g_m0[(size_t)n * H + j] = acc;
}
__global__ void k_prep_c(const float* __restrict__ wih0, const float* __restrict__ db,
                         const float* __restrict__ bih0) {
    int n = blockIdx.x * blockDim.x + threadIdx.x;
    if (n < H3) {
        float a = 0.f;
        #pragma unroll 8
        for (int k = 0; k < H; k++) a = fmaf(wih0[(size_t)n * H + k], db[k], a);
        g_c0[n] = a + bih0[n];
    }
}
// fp32 -> 2 fp16 planes with pre-scale (n4 = elements/4)
__global__ void k_split(const float* __restrict__ src,
                        __half* __restrict__ dh, __half* __restrict__ dl,
                        float pre, int n4) {
    int i = blockIdx.x * blockDim.x + threadIdx.x;
    int stride = gridDim.x * blockDim.x;
    for (; i < n4; i += stride) {
        float4 f = ((const float4*)src)[i];
        __half h[4], l[4];
        split2s(f.x, pre, h[0], l[0]);
        split2s(f.y, pre, h[1], l[1]);
        split2s(f.z, pre, h[2], l[2]);
        split2s(f.w, pre, h[3], l[3]);
        uint2 uh = {pack2h(h[0], h[1]), pack2h(h[2], h[3])};
        uint2 ul = {pack2h(l[0], l[1]), pack2h(l[2], l[3])};
        ((uint2*)dh)[i] = uh;
        ((uint2*)dl)[i] = ul;
    }
}

// ---------------- fp16 GEMM, 2-plane scaled operands, 3 products ------------
// true C = (accHH*4096 + accLO*2) + bias  (A pre-scaled 2^-12, lo planes x2048)
// HH: fresh zero-C + RN scalar adds. HL, LH chained into accLO.
__global__ void __launch_bounds__(256, 2)
gemm_mma(const __half* __restrict__ Ah, const __half* __restrict__ Al,
         const __half* __restrict__ Wh, const __half* __restrict__ Wl,
         const float* __restrict__ bias, float* __restrict__ C,
         const int* __restrict__ offPtr, const int* __restrict__ cntPtr,
         int Mfixed, int Ncols)
{
    extern __shared__ __align__(128) char smem[];
    const uint32_t sb = smem_u32(smem);

    const int tid = threadIdx.x;
    const int lane = tid & 31;
    const int wid = tid >> 5;
    const int wm = wid & 3;
    const int wn = wid >> 2;

    const int M = cntPtr ? *cntPtr : Mfixed;
    const int aoff = offPtr ? *offPtr : 0;
    const int mtiles = (M + 127) >> 7;
    const int ntiles = Ncols >> 6;
    const int total = mtiles * ntiles;

    const __half* pA[2] = {Ah, Al};
    const __half* pW[2] = {Wh, Wl};

    uint32_t sA[4]; int rA[4], qA[4], plA[4];
    #pragma unroll
    for (int i = 0; i < 4; i++) {
        int u = i * 256 + tid;
        plA[i] = u >> 9; int rem = u & 511; rA[i] = rem >> 2; qA[i] = rem & 3;
        sA[i] = (uint32_t)(plA[i] * ASPL + rA[i] * LDA + qA[i] * 16);
    }
    uint32_t sW[2]; int rW[2], qW[2], plW[2];
    #pragma unroll
    for (int i = 0; i < 2; i++) {
        int u = i * 256 + tid;
        plW[i] = u >> 8; int rem = u & 255; rW[i] = rem >> 2; qW[i] = rem & 3;
        sW[i] = (uint32_t)(OFF_W + plW[i] * WSPL + rW[i] * LDA + qW[i] * 16);
    }

    uint32_t a_ld[2];
    #pragma unroll
    for (int mt = 0; mt < 2; mt++) {
        int r = wm * 32 + mt * 16 + (lane & 15);
        a_ld[mt] = sb + (uint32_t)(r * LDA + (lane >> 4) * 16);
    }
    uint32_t w_ld[2];
    #pragma unroll
    for (int bp = 0; bp < 2; bp++) {
        int n = wn * 32 + bp * 16 + (lane >> 4) * 8 + (lane & 7);
        int half = (lane >> 3) & 1;
        w_ld[bp] = sb + (uint32_t)(OFF_W + n * LDA + half * 16);
    }

    for (int t = blockIdx.x; t < total; t += gridDim.x) {
        int tm = t % mtiles, tn = t / mtiles;
        int row0 = tm << 7, cb = tn << 6;
        int arow0 = aoff + row0;

        const __half* gA[4];
        #pragma unroll
        for (int i = 0; i < 4; i++)
            gA[i] = pA[plA[i]] + (size_t)(arow0 + rA[i]) * H + qA[i] * 8;
        const __half* gW[2];
        #pragma unroll
        for (int i = 0; i < 2; i++)
            gW[i] = pW[plW[i]] + (size_t)(cb + rW[i]) * H + qW[i] * 8;

        #pragma unroll
        for (int i = 0; i < 4; i++) cp16(sb + sA[i], gA[i]);
        #pragma unroll
        for (int i = 0; i < 2; i++) cp16(sb + sW[i], gW[i]);
        asm volatile("cp.async.commit_group;" ::: "memory");
        asm volatile("cp.async.wait_group 0;" ::: "memory");
        __syncthreads();

        float accHH[2][4][4] = {};
        float accLO[2][4][4] = {};

        #pragma unroll 1
        for (int kc = 0; kc < NCH; kc++) {
            uint32_t st = (uint32_t)((kc & 1) * STAGE);
            if (kc < NCH - 1) {
                uint32_t stn = (uint32_t)(((kc + 1) & 1) * STAGE);
                #pragma unroll
                for (int i = 0; i < 4; i++) cp16(sb + stn + sA[i], gA[i] + (kc + 1) * 32);
                #pragma unroll
                for (int i = 0; i < 2; i++) cp16(sb + stn + sW[i], gW[i] + (kc + 1) * 32);
                asm volatile("cp.async.commit_group;" ::: "memory");
            }
            #pragma unroll
            for (int ks = 0; ks < 2; ks++) {
                uint32_t bf[2][4][2];
                #pragma unroll
                for (int s = 0; s < 2; s++) {
                    #pragma unroll
                    for (int bp = 0; bp < 2; bp++) {
                        uint32_t wd = w_ld[bp] + st + ks * 32 + (uint32_t)s * WSPL;
                        uint32_t r0, r1, r2, r3;
                        ldsm4(r0, r1, r2, r3, wd);
                        bf[s][bp * 2][0] = r0;  bf[s][bp * 2][1] = r1;
                        bf[s][bp * 2 + 1][0] = r2;  bf[s][bp * 2 + 1][1] = r3;
                    }
                }
                // A hi: HH fresh + HL chained
                {
                    uint32_t af[2][4];
                    #pragma unroll
                    for (int mt = 0; mt < 2; mt++) {
                        uint32_t ad = a_ld[mt] + st + ks * 32;
                        ldsm4(af[mt][0], af[mt][1], af[mt][2], af[mt][3], ad);
                    }
                    #pragma unroll
                    for (int mt = 0; mt < 2; mt++)
                        #pragma unroll
                        for (int nt = 0; nt < 4; nt++) {
                            float tmp[4] = {0.f, 0.f, 0.f, 0.f};
                            mma16816(tmp, af[mt], bf[0][nt]);
                            accHH[mt][nt][0] += tmp[0];
                            accHH[mt][nt][1] += tmp[1];
                            accHH[mt][nt][2] += tmp[2];
                            accHH[mt][nt][3] += tmp[3];
                            mma16816(accLO[mt][nt], af[mt], bf[1][nt]);
                        }
                }
                // A lo: LH chained
                {
                    uint32_t af[2][4];
                    #pragma unroll
                    for (int mt = 0; mt < 2; mt++) {
                        uint32_t ad = a_ld[mt] + st + ks * 32 + (uint32_t)ASPL;
                        ldsm4(af[mt][0], af[mt][1], af[mt][2], af[mt][3], ad);
                    }
                    #pragma unroll
                    for (int mt = 0; mt < 2; mt++)
                        #pragma unroll
                        for (int nt = 0; nt < 4; nt++)
                            mma16816(accLO[mt][nt], af[mt], bf[0][nt]);
                }
            }
            if (kc < NCH - 1) {
                asm volatile("cp.async.wait_group 0;" ::: "memory");
                __syncthreads();
            }
        }

        // epilogue: (HH*4096 + LO*2) + bias
        #pragma unroll
        for (int mt = 0; mt < 2; mt++) {
            #pragma unroll
            for (int p = 0; p < 2; p++) {
                int gm = row0 + wm * 32 + mt * 16 + (lane >> 2) + p * 8;
                if (gm < M) {
                    float* dst = C + (size_t)(aoff + gm) * Ncols;
                    #pragma unroll
                    for (int nt = 0; nt < 4; nt++) {
                        int col = cb + wn * 32 + nt * 8 + (lane & 3) * 2;
                        float2 o;
                        o.x = fmaf(accHH[mt][nt][p * 2 + 0], 4096.0f,
                                   accLO[mt][nt][p * 2 + 0] * 2.0f) + __ldg(bias + col);
                        o.y = fmaf(accHH[mt][nt][p * 2 + 1], 4096.0f,
                                   accLO[mt][nt][p * 2 + 1] * 2.0f) + __ldg(bias + col + 1);
                        *(float2*)(dst + col) = o;
                    }
                }
            }
        }
    }
}

// ---------------- per-sweep aggregation: fp32 + scaled splits ----------------
__device__ __forceinline__ void store_split4(size_t off, float4 f) {
    __half h[4], l[4];
    split2s(f.x, ASCALE, h[0], l[0]);
    split2s(f.y, ASCALE, h[1], l[1]);
    split2s(f.z, ASCALE, h[2], l[2]);
    split2s(f.w, ASCALE, h[3], l[3]);
    uint2 uh = {pack2h(h[0], h[1]), pack2h(h[2], h[3])};
    uint2 ul = {pack2h(l[0], l[1]), pack2h(l[2], l[3])};
    *(uint2*)(g_aggs[0] + off) = uh;
    *(uint2*)(g_aggs[1] + off) = ul;
}
__global__ void k_gather(const float* __restrict__ hsrc, int sweep) {
    int gw = (blockIdx.x * blockDim.x + threadIdx.x) >> 5;
    int nw = (gridDim.x * blockDim.x) >> 5;
    int lane = threadIdx.x & 31;
    int cnt = g_cnt[sweep], base = g_off[sweep];
    for (int i = gw; i < cnt; i += nw) {
        int node = g_order[base + i];
        int e0 = g_csr_off[node], e1 = g_csr_off[node + 1];
        float4 a0 = make_float4(0.f, 0.f, 0.f, 0.f);
        float4 a1 = make_float4(0.f, 0.f, 0.f, 0.f);
        for (int e = e0; e < e1; e++) {
            int src = g_csr_src[e];
            const float4* r = (const float4*)(hsrc + (size_t)src * H);
            float4 x0 = r[lane], x1 = r[lane + 32];
            a0.x += x0.x; a0.y += x0.y; a0.z += x0.z; a0.w += x0.w;
            a1.x += x1.x; a1.y += x1.y; a1.z += x1.z; a1.w += x1.w;
        }
        size_t orow = (size_t)(base + i) * H;
        float4* o = (float4*)(g_agg + orow);
        o[lane] = a0; o[lane + 32] = a1;
        store_split4(orow + lane * 4, a0);
        store_split4(orow + 128 + lane * 4, a1);
    }
}

// ---------------- per-sweep GRU epilogue ------------------------------------
__global__ void k_gru(float* __restrict__ hout, int sweep,
                      const float* __restrict__ ghp, int per_node, int wsplit) {
    int cnt = g_cnt[sweep], base = g_off[sweep];
    int j = threadIdx.x;
    for (int i = blockIdx.x; i < cnt; i += gridDim.x) {
        int node = g_order[base + i];
        const float* gi = g_gi + (size_t)node * H3;
        const float* gh = per_node ? (ghp + (size_t)(base + i) * H3) : ghp;
        float ir = gi[j], iz = gi[j + H], in_ = gi[j + 2 * H];
        float hr = gh[j], hz = gh[j + H], hn = gh[j + 2 * H];
        float a = per_node ? g_agg[(size_t)(base + i) * H + j] : 0.f;
        float r = 1.f / (1.f + expf(-(ir + hr)));
        float z = 1.f / (1.f + expf(-(iz + hz)));
        float n = tanhf(in_ + r * hn);
        float hv = (1.f - z) * n + z * a;
        hout[(size_t)node * H + j] = hv;
        if (wsplit) {
            __half sh, sl;
            split2s(hv, ASCALE, sh, sl);
            size_t o = (size_t)node * H + j;
            g_xs[0][o] = sh; g_xs[1][o] = sl;
        }
    }
}

// ---------------- launch -----------------------------------------------------
extern "C" void kernel_launch(void* const* d_in, const int* in_sizes, int n_in,
                              void* d_out, int out_size) {
    const float* V   = (const float*)d_in[0];
    const int*   E   = (const int*)d_in[1];
    const float* dw  = (const float*)d_in[2];
    const float* db  = (const float*)d_in[3];
    const float* wih = (const float*)d_in[4];
    const float* whh = (const float*)d_in[5];
    const float* bih = (const float*)d_in[6];
    const float* bhh = (const float*)d_in[7];
    float* out = (float*)d_out;

    float *p_h1, *p_gi, *p_gh, *p_m0, *p_c0;
    __half *p_xs, *p_aggs, *p_ws;
    int *p_cnt, *p_off;
    cudaGetSymbolAddress((void**)&p_h1,  g_h1);
    cudaGetSymbolAddress((void**)&p_gi,  g_gi);
    cudaGetSymbolAddress((void**)&p_gh,  g_gh);
    cudaGetSymbolAddress((void**)&p_m0,  g_m0);
    cudaGetSymbolAddress((void**)&p_c0,  g_c0);
    cudaGetSymbolAddress((void**)&p_xs,  g_xs);
    cudaGetSymbolAddress((void**)&p_aggs, g_aggs);
    cudaGetSymbolAddress((void**)&p_ws,  g_ws);
    cudaGetSymbolAddress((void**)&p_cnt, g_cnt);
    cudaGetSymbolAddress((void**)&p_off, g_off);

    cudaFuncSetAttribute(gemm_mma, cudaFuncAttributeMaxDynamicSharedMemorySize, SMEM_TOT);

    // ---- schedule ----
    k_init<<<256, 256>>>();
    for (int p = 0; p < NL - 1; p++) k_relax<<<1024, 256>>>(E);
    k_indeg<<<1024, 256>>>(E);
    k_count<<<256, 256>>>();
    k_off8<<<1, 1>>>();
    k_scan<<<1, 1024>>>();
    k_scatter_node<<<256, 256>>>();
    k_scatter_edge<<<1024, 256>>>(E);

    // ---- fused weights + W splits (unscaled) ----
    k_prep<<<H3, 256>>>(wih, dw);
    k_prep_c<<<3, 256>>>(wih, db, bih);

    const int WN4 = (H3 * H) / 4;
    const size_t WPL = (size_t)H3 * H;
    // mat0 = m0, mat1 = wih1, mat2 = whh0, mat3 = whh1 (2 planes each)
    k_split<<<512, 256>>>(p_m0, p_ws + 0 * WPL, p_ws + 1 * WPL, 1.0f, WN4);
    k_split<<<512, 256>>>(wih + WPL, p_ws + 2 * WPL, p_ws + 3 * WPL, 1.0f, WN4);
    k_split<<<512, 256>>>(whh, p_ws + 4 * WPL, p_ws + 5 * WPL, 1.0f, WN4);
    k_split<<<512, 256>>>(whh + WPL, p_ws + 6 * WPL, p_ws + 7 * WPL, 1.0f, WN4);

    // ---- V splits (scaled) ----
    const size_t XPL = (size_t)NP * H;
    k_split<<<1024, 256>>>(V, p_xs, p_xs + XPL, ASCALE, (NN * H) / 4);

    for (int l = 0; l < 2; l++) {
        float* hout = l ? out : p_h1;
        const float* bih_l = bih + (size_t)l * H3;
        const float* bhh_l = bhh + (size_t)l * H3;
        const __half* wgi = p_ws + (size_t)(l ? 2 : 0) * WPL;
        const __half* wgh = p_ws + (size_t)(l ? 6 : 4) * WPL;
        const float* gibias = l ? bih_l : p_c0;

        gemm_mma<<<1184, 256, SMEM_TOT>>>(p_xs, p_xs + XPL,
                                          wgi, wgi + WPL,
                                          gibias, p_gi, nullptr, nullptr, NN, H3);

        // sweep 0: agg = 0 -> gh = bhh exactly
        k_gru<<<2048, 256>>>(hout, 0, bhh_l, 0, l == 0 ? 1 : 0);

        for (int s = 1; s < NL; s++) {
            k_gather<<<1024, 256>>>(hout, s);
            gemm_mma<<<592, 256, SMEM_TOT>>>(p_aggs, p_aggs + XPL,
                                             wgh, wgh + WPL,
                                             bhh_l, p_gh, p_off + s, p_cnt + s, 0, H3);
            k_gru<<<2048, 256>>>(hout, s, p_gh, 1, l == 0 ? 1 : 0);
        }
    }
}

// round 13
// speedup vs baseline: 2.0089x; 1.1025x over previous
#include <cuda_runtime.h>
#include <cuda_fp16.h>
#include <math.h>
#include <stdint.h>

#define NN 50000
#define NP (NN + 128)
#define NE 400000
#define H  256
#define H3 768
#define NL 8

#define BM 128
#define BN 64
#define BK 32
#define NCH 8

// smem: rows padded to 80B -> conflict-free ldmatrix
#define LDA 80
#define ASPL (128 * LDA)             // 10240 per A plane
#define WSPL (64 * LDA)              // 5120 per W plane
#define OFF_W (2 * ASPL)             // 20480
#define STAGE (2 * ASPL + 2 * WSPL)  // 30720
#define SMEM_TOT (2 * STAGE)         // 61440

#define ASCALE (1.0f / 4096.0f)      // A-side pre-scale (2^-12)
#define LOSC   2048.0f               // lo-plane boost (2^11)

// ---------------- scratch (static device globals) --------------------------
__device__ float g_h1[NN * H];
__device__ float g_gi[NN * H3];
__device__ float g_gh[NN * H3];
__device__ float g_m0[H3 * H];
__device__ float g_c0[H3];

__device__ __half g_xs[2][NP * H];   // gi-input splits (scaled by 2^-12)
__device__ __half g_aggs[2][NP * H]; // agg splits (scaled, compacted)
__device__ __half g_ws[8 * H3 * H];  // 4 W mats x 2 planes (unscaled)

__device__ int g_depth[NN];
__device__ int g_indeg[NN];
__device__ int g_csr_off[NN + 1];
__device__ int g_csr_fill[NN];
__device__ int g_csr_src[NE];
__device__ int g_order[NN];
__device__ int g_cnt[NL];
__device__ int g_off[NL + 1];
__device__ int g_fill[NL];

// ---------------- helpers ---------------------------------------------------
__device__ __forceinline__ uint32_t smem_u32(const void* p) {
    uint32_t a;
    asm("{ .reg .u64 t; cvta.to.shared.u64 t, %1; cvt.u32.u64 %0, t; }" : "=r"(a) : "l"(p));
    return a;
}
__device__ __forceinline__ void ldsm4(uint32_t& r0, uint32_t& r1, uint32_t& r2, uint32_t& r3,
                                      uint32_t a) {
    asm volatile("ldmatrix.sync.aligned.m8n8.x4.shared.b16 {%0,%1,%2,%3}, [%4];"
                 : "=r"(r0), "=r"(r1), "=r"(r2), "=r"(r3) : "r"(a));
}
__device__ __forceinline__ void mma16816(float* d, const uint32_t* a, const uint32_t* b) {
    asm volatile(
        "mma.sync.aligned.m16n8k16.row.col.f32.f16.f16.f32 "
        "{%0,%1,%2,%3}, {%4,%5,%6,%7}, {%8,%9}, {%0,%1,%2,%3};"
        : "+f"(d[0]), "+f"(d[1]), "+f"(d[2]), "+f"(d[3])
        : "r"(a[0]), "r"(a[1]), "r"(a[2]), "r"(a[3]), "r"(b[0]), "r"(b[1]));
}
__device__ __forceinline__ void cp16(uint32_t s, const void* g) {
    asm volatile("cp.async.ca.shared.global [%0], [%1], 16;" :: "r"(s), "l"(g) : "memory");
}
// 2-way fp16 split with pre-scale: h = rn(x*pre), l = rn((x*pre - h)*2048)
__device__ __forceinline__ void split2s(float x, float pre, __half& h, __half& l) {
    float xs = x * pre;
    h = __float2half_rn(xs);
    l = __float2half_rn((xs - __half2float(h)) * LOSC);
}
__device__ __forceinline__ uint32_t pack2h(__half a, __half b) {
    return (uint32_t)__half_as_ushort(b) << 16 | __half_as_ushort(a);
}

// ---------------- schedule construction ------------------------------------
__global__ void k_init() {
    int i = blockIdx.x * blockDim.x + threadIdx.x;
    int stride = gridDim.x * blockDim.x;
    for (int n = i; n < NN; n += stride) {
        g_depth[n] = 0; g_indeg[n] = 0; g_csr_fill[n] = 0;
    }
    if (i < NL) { g_cnt[i] = 0; g_fill[i] = 0; }
}
__global__ void k_relax(const int* __restrict__ E) {
    int i = blockIdx.x * blockDim.x + threadIdx.x;
    int stride = gridDim.x * blockDim.x;
    for (int e = i; e < NE; e += stride) {
        int s = E[e], d = E[NE + e];
        atomicMax(&g_depth[d], g_depth[s] + 1);
    }
}
__global__ void k_indeg(const int* __restrict__ E) {
    int i = blockIdx.x * blockDim.x + threadIdx.x;
    int stride = gridDim.x * blockDim.x;
    for (int e = i; e < NE; e += stride) atomicAdd(&g_indeg[E[NE + e]], 1);
}
__global__ void k_count() {
    int i = blockIdx.x * blockDim.x + threadIdx.x;
    int stride = gridDim.x * blockDim.x;
    for (int n = i; n < NN; n += stride) atomicAdd(&g_cnt[g_depth[n]], 1);
}
__global__ void k_off8() {
    g_off[0] = 0;
    for (int d = 0; d < NL; d++) g_off[d + 1] = g_off[d] + g_cnt[d];
}
__global__ void k_scan() {
    __shared__ int sh[1024];
    __shared__ int carry;
    int tid = threadIdx.x;
    if (tid == 0) carry = 0;
    __syncthreads();
    for (int base = 0; base < NN; base += 1024) {
        int i = base + tid;
        int v = (i < NN) ? g_indeg[i] : 0;
        sh[tid] = v;
        __syncthreads();
        for (int ofs = 1; ofs < 1024; ofs <<= 1) {
            int t = (tid >= ofs) ? sh[tid - ofs] : 0;
            __syncthreads();
            sh[tid] += t;
            __syncthreads();
        }
        if (i < NN) g_csr_off[i] = carry + sh[tid] - v;
        __syncthreads();
        if (tid == 0) carry += sh[1023];
        __syncthreads();
    }
    if (tid == 0) g_csr_off[NN] = carry;
}
__global__ void k_scatter_node() {
    int i = blockIdx.x * blockDim.x + threadIdx.x;
    int stride = gridDim.x * blockDim.x;
    for (int n = i; n < NN; n += stride) {
        int d = g_depth[n];
        int pos = g_off[d] + atomicAdd(&g_fill[d], 1);
        g_order[pos] = n;
    }
}
__global__ void k_scatter_edge(const int* __restrict__ E) {
    int i = blockIdx.x * blockDim.x + threadIdx.x;
    int stride = gridDim.x * blockDim.x;
    for (int e = i; e < NE; e += stride) {
        int d = E[NE + e];
        int pos = g_csr_off[d] + atomicAdd(&g_csr_fill[d], 1);
        g_csr_src[pos] = E[e];
    }
}

// ---------------- fused-weight precompute + splits ---------------------------
__global__ void k_prep(const float* __restrict__ wih0, const float* __restrict__ dw) {
    __shared__ float wrow[H];
    int n = blockIdx.x;
    int j = threadIdx.x;
    wrow[j] = wih0[(size_t)n * H + j];
    __syncthreads();
    float acc = 0.f;
    #pragma unroll 8
    for (int k = 0; k < H; k++) acc = fmaf(wrow[k], dw[(size_t)k * H + j], acc);
    g_m0[(size_t)n * H + j] = acc;
}
__global__ void k_prep_c(const float* __restrict__ wih0, const float* __restrict__ db,
                         const float* __restrict__ bih0) {
    int n = blockIdx.x * blockDim.x + threadIdx.x;
    if (n < H3) {
        float a = 0.f;
        #pragma unroll 8
        for (int k = 0; k < H; k++) a = fmaf(wih0[(size_t)n * H + k], db[k], a);
        g_c0[n] = a + bih0[n];
    }
}
// fp32 -> 2 fp16 planes with pre-scale (n4 = elements/4)
__global__ void k_split(const float* __restrict__ src,
                        __half* __restrict__ dh, __half* __restrict__ dl,
                        float pre, int n4) {
    int i = blockIdx.x * blockDim.x + threadIdx.x;
    int stride = gridDim.x * blockDim.x;
    for (; i < n4; i += stride) {
        float4 f = ((const float4*)src)[i];
        __half h[4], l[4];
        split2s(f.x, pre, h[0], l[0]);
        split2s(f.y, pre, h[1], l[1]);
        split2s(f.z, pre, h[2], l[2]);
        split2s(f.w, pre, h[3], l[3]);
        uint2 uh = {pack2h(h[0], h[1]), pack2h(h[2], h[3])};
        uint2 ul = {pack2h(l[0], l[1]), pack2h(l[2], l[3])};
        ((uint2*)dh)[i] = uh;
        ((uint2*)dl)[i] = ul;
    }
}

// ---------------- fp16 GEMM, 2-plane scaled operands, 3 products ------------
// true C = (accHH*4096 + accLO*2) + bias  (A pre-scaled 2^-12, lo planes x2048)
// HH: fresh zero-C + RN scalar adds. HL, LH chained into accLO.
__global__ void __launch_bounds__(256, 2)
gemm_mma(const __half* __restrict__ Ah, const __half* __restrict__ Al,
         const __half* __restrict__ Wh, const __half* __restrict__ Wl,
         const float* __restrict__ bias, float* __restrict__ C,
         const int* __restrict__ offPtr, const int* __restrict__ cntPtr,
         int Mfixed, int Ncols)
{
    extern __shared__ __align__(128) char smem[];
    const uint32_t sb = smem_u32(smem);

    const int tid = threadIdx.x;
    const int lane = tid & 31;
    const int wid = tid >> 5;
    const int wm = wid & 3;
    const int wn = wid >> 2;

    const int M = cntPtr ? *cntPtr : Mfixed;
    const int aoff = offPtr ? *offPtr : 0;
    const int mtiles = (M + 127) >> 7;
    const int ntiles = Ncols >> 6;
    const int total = mtiles * ntiles;

    const __half* pA[2] = {Ah, Al};
    const __half* pW[2] = {Wh, Wl};

    uint32_t sA[4]; int rA[4], qA[4], plA[4];
    #pragma unroll
    for (int i = 0; i < 4; i++) {
        int u = i * 256 + tid;
        plA[i] = u >> 9; int rem = u & 511; rA[i] = rem >> 2; qA[i] = rem & 3;
        sA[i] = (uint32_t)(plA[i] * ASPL + rA[i] * LDA + qA[i] * 16);
    }
    uint32_t sW[2]; int rW[2], qW[2], plW[2];
    #pragma unroll
    for (int i = 0; i < 2; i++) {
        int u = i * 256 + tid;
        plW[i] = u >> 8; int rem = u & 255; rW[i] = rem >> 2; qW[i] = rem & 3;
        sW[i] = (uint32_t)(OFF_W + plW[i] * WSPL + rW[i] * LDA + qW[i] * 16);
    }

    uint32_t a_ld[2];
    #pragma unroll
    for (int mt = 0; mt < 2; mt++) {
        int r = wm * 32 + mt * 16 + (lane & 15);
        a_ld[mt] = sb + (uint32_t)(r * LDA + (lane >> 4) * 16);
    }
    uint32_t w_ld[2];
    #pragma unroll
    for (int bp = 0; bp < 2; bp++) {
        int n = wn * 32 + bp * 16 + (lane >> 4) * 8 + (lane & 7);
        int half = (lane >> 3) & 1;
        w_ld[bp] = sb + (uint32_t)(OFF_W + n * LDA + half * 16);
    }

    for (int t = blockIdx.x; t < total; t += gridDim.x) {
        int tm = t % mtiles, tn = t / mtiles;
        int row0 = tm << 7, cb = tn << 6;
        int arow0 = aoff + row0;

        const __half* gA[4];
        #pragma unroll
        for (int i = 0; i < 4; i++)
            gA[i] = pA[plA[i]] + (size_t)(arow0 + rA[i]) * H + qA[i] * 8;
        const __half* gW[2];
        #pragma unroll
        for (int i = 0; i < 2; i++)
            gW[i] = pW[plW[i]] + (size_t)(cb + rW[i]) * H + qW[i] * 8;

        #pragma unroll
        for (int i = 0; i < 4; i++) cp16(sb + sA[i], gA[i]);
        #pragma unroll
        for (int i = 0; i < 2; i++) cp16(sb + sW[i], gW[i]);
        asm volatile("cp.async.commit_group;" ::: "memory");
        asm volatile("cp.async.wait_group 0;" ::: "memory");
        __syncthreads();

        float accHH[2][4][4] = {};
        float accLO[2][4][4] = {};

        #pragma unroll 1
        for (int kc = 0; kc < NCH; kc++) {
            uint32_t st = (uint32_t)((kc & 1) * STAGE);
            if (kc < NCH - 1) {
                uint32_t stn = (uint32_t)(((kc + 1) & 1) * STAGE);
                #pragma unroll
                for (int i = 0; i < 4; i++) cp16(sb + stn + sA[i], gA[i] + (kc + 1) * 32);
                #pragma unroll
                for (int i = 0; i < 2; i++) cp16(sb + stn + sW[i], gW[i] + (kc + 1) * 32);
                asm volatile("cp.async.commit_group;" ::: "memory");
            }
            #pragma unroll
            for (int ks = 0; ks < 2; ks++) {
                uint32_t bf[2][4][2];
                #pragma unroll
                for (int s = 0; s < 2; s++) {
                    #pragma unroll
                    for (int bp = 0; bp < 2; bp++) {
                        uint32_t wd = w_ld[bp] + st + ks * 32 + (uint32_t)s * WSPL;
                        uint32_t r0, r1, r2, r3;
                        ldsm4(r0, r1, r2, r3, wd);
                        bf[s][bp * 2][0] = r0;  bf[s][bp * 2][1] = r1;
                        bf[s][bp * 2 + 1][0] = r2;  bf[s][bp * 2 + 1][1] = r3;
                    }
                }
                // A hi: HH fresh + HL chained
                {
                    uint32_t af[2][4];
                    #pragma unroll
                    for (int mt = 0; mt < 2; mt++) {
                        uint32_t ad = a_ld[mt] + st + ks * 32;
                        ldsm4(af[mt][0], af[mt][1], af[mt][2], af[mt][3], ad);
                    }
                    #pragma unroll
                    for (int mt = 0; mt < 2; mt++)
                        #pragma unroll
                        for (int nt = 0; nt < 4; nt++) {
                            float tmp[4] = {0.f, 0.f, 0.f, 0.f};
                            mma16816(tmp, af[mt], bf[0][nt]);
                            accHH[mt][nt][0] += tmp[0];
                            accHH[mt][nt][1] += tmp[1];
                            accHH[mt][nt][2] += tmp[2];
                            accHH[mt][nt][3] += tmp[3];
                            mma16816(accLO[mt][nt], af[mt], bf[1][nt]);
                        }
                }
                // A lo: LH chained
                {
                    uint32_t af[2][4];
                    #pragma unroll
                    for (int mt = 0; mt < 2; mt++) {
                        uint32_t ad = a_ld[mt] + st + ks * 32 + (uint32_t)ASPL;
                        ldsm4(af[mt][0], af[mt][1], af[mt][2], af[mt][3], ad);
                    }
                    #pragma unroll
                    for (int mt = 0; mt < 2; mt++)
                        #pragma unroll
                        for (int nt = 0; nt < 4; nt++)
                            mma16816(accLO[mt][nt], af[mt], bf[0][nt]);
                }
            }
            if (kc < NCH - 1) {
                asm volatile("cp.async.wait_group 0;" ::: "memory");
                __syncthreads();
            }
        }

        // epilogue: (HH*4096 + LO*2) + bias
        #pragma unroll
        for (int mt = 0; mt < 2; mt++) {
            #pragma unroll
            for (int p = 0; p < 2; p++) {
                int gm = row0 + wm * 32 + mt * 16 + (lane >> 2) + p * 8;
                if (gm < M) {
                    float* dst = C + (size_t)(aoff + gm) * Ncols;
                    #pragma unroll
                    for (int nt = 0; nt < 4; nt++) {
                        int col = cb + wn * 32 + nt * 8 + (lane & 3) * 2;
                        float2 o;
                        o.x = fmaf(accHH[mt][nt][p * 2 + 0], 4096.0f,
                                   accLO[mt][nt][p * 2 + 0] * 2.0f) + __ldg(bias + col);
                        o.y = fmaf(accHH[mt][nt][p * 2 + 1], 4096.0f,
                                   accLO[mt][nt][p * 2 + 1] * 2.0f) + __ldg(bias + col + 1);
                        *(float2*)(dst + col) = o;
                    }
                }
            }
        }
    }
}

// ---------------- per-sweep aggregation: scaled split planes only -----------
__device__ __forceinline__ void store_split4(size_t off, float4 f) {
    __half h[4], l[4];
    split2s(f.x, ASCALE, h[0], l[0]);
    split2s(f.y, ASCALE, h[1], l[1]);
    split2s(f.z, ASCALE, h[2], l[2]);
    split2s(f.w, ASCALE, h[3], l[3]);
    uint2 uh = {pack2h(h[0], h[1]), pack2h(h[2], h[3])};
    uint2 ul = {pack2h(l[0], l[1]), pack2h(l[2], l[3])};
    *(uint2*)(g_aggs[0] + off) = uh;
    *(uint2*)(g_aggs[1] + off) = ul;
}
__global__ void k_gather(const float* __restrict__ hsrc, int sweep) {
    int gw = (blockIdx.x * blockDim.x + threadIdx.x) >> 5;
    int nw = (gridDim.x * blockDim.x) >> 5;
    int lane = threadIdx.x & 31;
    int cnt = g_cnt[sweep], base = g_off[sweep];
    for (int i = gw; i < cnt; i += nw) {
        int node = g_order[base + i];
        int e0 = g_csr_off[node], e1 = g_csr_off[node + 1];
        float4 a0 = make_float4(0.f, 0.f, 0.f, 0.f);
        float4 a1 = make_float4(0.f, 0.f, 0.f, 0.f);
        for (int e = e0; e < e1; e++) {
            int src = g_csr_src[e];
            const float4* r = (const float4*)(hsrc + (size_t)src * H);
            float4 x0 = r[lane], x1 = r[lane + 32];
            a0.x += x0.x; a0.y += x0.y; a0.z += x0.z; a0.w += x0.w;
            a1.x += x1.x; a1.y += x1.y; a1.z += x1.z; a1.w += x1.w;
        }
        size_t orow = (size_t)(base + i) * H;
        store_split4(orow + lane * 4, a0);
        store_split4(orow + 128 + lane * 4, a1);
    }
}

// ---------------- per-sweep GRU epilogue ------------------------------------
__global__ void k_gru(float* __restrict__ hout, int sweep,
                      const float* __restrict__ ghp, int per_node, int wsplit) {
    int cnt = g_cnt[sweep], base = g_off[sweep];
    int j = threadIdx.x;
    for (int i = blockIdx.x; i < cnt; i += gridDim.x) {
        int node = g_order[base + i];
        const float* gi = g_gi + (size_t)node * H3;
        const float* gh = per_node ? (ghp + (size_t)(base + i) * H3) : ghp;
        float ir = gi[j], iz = gi[j + H], in_ = gi[j + 2 * H];
        float hr = gh[j], hz = gh[j + H], hn = gh[j + 2 * H];
        float a = 0.f;
        if (per_node) {
            size_t o2 = (size_t)(base + i) * H + j;
            a = __half2float(g_aggs[0][o2]) * 4096.0f
              + __half2float(g_aggs[1][o2]) * 2.0f;
        }
        float r = 1.f / (1.f + expf(-(ir + hr)));
        float z = 1.f / (1.f + expf(-(iz + hz)));
        float n = tanhf(in_ + r * hn);
        float hv = (1.f - z) * n + z * a;
        hout[(size_t)node * H + j] = hv;
        if (wsplit) {
            __half sh, sl;
            split2s(hv, ASCALE, sh, sl);
            size_t o = (size_t)node * H + j;
            g_xs[0][o] = sh; g_xs[1][o] = sl;
        }
    }
}

// ---------------- launch -----------------------------------------------------
extern "C" void kernel_launch(void* const* d_in, const int* in_sizes, int n_in,
                              void* d_out, int out_size) {
    const float* V   = (const float*)d_in[0];
    const int*   E   = (const int*)d_in[1];
    const float* dw  = (const float*)d_in[2];
    const float* db  = (const float*)d_in[3];
    const float* wih = (const float*)d_in[4];
    const float* whh = (const float*)d_in[5];
    const float* bih = (const float*)d_in[6];
    const float* bhh = (const float*)d_in[7];
    float* out = (float*)d_out;

    float *p_h1, *p_gi, *p_gh, *p_m0, *p_c0;
    __half *p_xs, *p_aggs, *p_ws;
    int *p_cnt, *p_off;
    cudaGetSymbolAddress((void**)&p_h1,  g_h1);
    cudaGetSymbolAddress((void**)&p_gi,  g_gi);
    cudaGetSymbolAddress((void**)&p_gh,  g_gh);
    cudaGetSymbolAddress((void**)&p_m0,  g_m0);
    cudaGetSymbolAddress((void**)&p_c0,  g_c0);
    cudaGetSymbolAddress((void**)&p_xs,  g_xs);
    cudaGetSymbolAddress((void**)&p_aggs, g_aggs);
    cudaGetSymbolAddress((void**)&p_ws,  g_ws);
    cudaGetSymbolAddress((void**)&p_cnt, g_cnt);
    cudaGetSymbolAddress((void**)&p_off, g_off);

    cudaFuncSetAttribute(gemm_mma, cudaFuncAttributeMaxDynamicSharedMemorySize, SMEM_TOT);

    // ---- fork side stream for the schedule chain (independent of weights) ----
    cudaStream_t s2;
    cudaStreamCreate(&s2);
    cudaEvent_t evA, evB;
    cudaEventCreateWithFlags(&evA, cudaEventDisableTiming);
    cudaEventCreateWithFlags(&evB, cudaEventDisableTiming);
    cudaEventRecord(evA, 0);
    cudaStreamWaitEvent(s2, evA, 0);

    k_init<<<256, 256, 0, s2>>>();
    for (int p = 0; p < NL - 1; p++) k_relax<<<1024, 256, 0, s2>>>(E);
    k_indeg<<<1024, 256, 0, s2>>>(E);
    k_count<<<256, 256, 0, s2>>>();
    k_off8<<<1, 1, 0, s2>>>();
    k_scan<<<1, 1024, 0, s2>>>();
    k_scatter_node<<<256, 256, 0, s2>>>();
    k_scatter_edge<<<1024, 256, 0, s2>>>(E);
    cudaEventRecord(evB, s2);
    // (stream/events intentionally not destroyed: destroying a forked stream
    //  mid-capture invalidates the graph; they hold no device memory)

    // ---- main stream: fused weights + W splits (overlaps schedule) ----
    k_prep<<<H3, 256>>>(wih, dw);
    k_prep_c<<<3, 256>>>(wih, db, bih);

    const int WN4 = (H3 * H) / 4;
    const size_t WPL = (size_t)H3 * H;
    k_split<<<512, 256>>>(p_m0, p_ws + 0 * WPL, p_ws + 1 * WPL, 1.0f, WN4);
    k_split<<<512, 256>>>(wih + WPL, p_ws + 2 * WPL, p_ws + 3 * WPL, 1.0f, WN4);
    k_split<<<512, 256>>>(whh, p_ws + 4 * WPL, p_ws + 5 * WPL, 1.0f, WN4);
    k_split<<<512, 256>>>(whh + WPL, p_ws + 6 * WPL, p_ws + 7 * WPL, 1.0f, WN4);

    const size_t XPL = (size_t)NP * H;
    k_split<<<1024, 256>>>(V, p_xs, p_xs + XPL, ASCALE, (NN * H) / 4);

    for (int l = 0; l < 2; l++) {
        float* hout = l ? out : p_h1;
        const float* bih_l = bih + (size_t)l * H3;
        const float* bhh_l = bhh + (size_t)l * H3;
        const __half* wgi = p_ws + (size_t)(l ? 2 : 0) * WPL;
        const __half* wgh = p_ws + (size_t)(l ? 6 : 4) * WPL;
        const float* gibias = l ? bih_l : p_c0;

        gemm_mma<<<1184, 256, SMEM_TOT>>>(p_xs, p_xs + XPL,
                                          wgi, wgi + WPL,
                                          gibias, p_gi, nullptr, nullptr, NN, H3);

        // join the schedule before its first consumer (sweep-0 k_gru)
        if (l == 0) cudaStreamWaitEvent(0, evB, 0);

        // sweep 0: agg = 0 -> gh = bhh exactly
        k_gru<<<2048, 256>>>(hout, 0, bhh_l, 0, l == 0 ? 1 : 0);

        for (int s = 1; s < NL; s++) {
            k_gather<<<1024, 256>>>(hout, s);
            gemm_mma<<<592, 256, SMEM_TOT>>>(p_aggs, p_aggs + XPL,
                                             wgh, wgh + WPL,
                                             bhh_l, p_gh, p_off + s, p_cnt + s, 0, H3);
            k_gru<<<2048, 256>>>(hout, s, p_gh, 1, l == 0 ? 1 : 0);
        }
    }
}